// round 2
// baseline (speedup 1.0000x reference)
#include <cuda_runtime.h>
#include <math.h>

#define S_   2048
#define HID_ 2048
#define NH_  16
#define NKV_ 4
#define GRP_ (NH_/NKV_)   // 4
#define HD_  128
#define KVD_ (NKV_*HD_)   // 512

// scratch (allocation-free: __device__ globals)
__device__ float g_q  [S_*HID_];   // Q projection, roped in place, [s][h*128+d]
__device__ float g_k  [S_*KVD_];   // K projection pre-rope, [s][kv*128+d]
__device__ float g_v  [S_*KVD_];   // V projection, [s][kv*128+d]
__device__ float g_att[S_*HID_];   // attention out, [s][h*128+d]

// ---------------------------------------------------------------------------
// SGEMM: C[M,N] = A[M,K] @ B[K,N]; BM=BN=128, BK=16; 256 thr, 8x8 microtile.
// ---------------------------------------------------------------------------
__global__ __launch_bounds__(256, 2)
void sgemm128(const float* __restrict__ A, const float* __restrict__ B,
              float* __restrict__ C, int M, int N, int K)
{
    __shared__ float As[16][128];   // transposed A tile: As[k][m]
    __shared__ float Bs[16][128];
    const int tid = threadIdx.x;
    const int tx  = tid & 15, ty = tid >> 4;
    const int bm  = blockIdx.y * 128, bn = blockIdx.x * 128;

    float acc[8][8];
    #pragma unroll
    for (int i = 0; i < 8; ++i)
        #pragma unroll
        for (int j = 0; j < 8; ++j) acc[i][j] = 0.f;

    for (int k0 = 0; k0 < K; k0 += 16) {
        #pragma unroll
        for (int q = 0; q < 2; ++q) {
            int slot = tid * 2 + q;                  // 0..511 float4 slots
            int m  = slot >> 2;
            int kc = (slot & 3) * 4;
            float4 a = *(const float4*)&A[(size_t)(bm + m) * K + k0 + kc];
            As[kc+0][m] = a.x; As[kc+1][m] = a.y;
            As[kc+2][m] = a.z; As[kc+3][m] = a.w;
            int row = slot >> 5;
            int c4  = (slot & 31) * 4;
            *(float4*)&Bs[row][c4] =
                *(const float4*)&B[(size_t)(k0 + row) * N + bn + c4];
        }
        __syncthreads();
        #pragma unroll
        for (int kk = 0; kk < 16; ++kk) {
            float a[8], b[8];
            *(float4*)&a[0] = *(float4*)&As[kk][ty*8];
            *(float4*)&a[4] = *(float4*)&As[kk][ty*8+4];
            *(float4*)&b[0] = *(float4*)&Bs[kk][tx*8];
            *(float4*)&b[4] = *(float4*)&Bs[kk][tx*8+4];
            #pragma unroll
            for (int i = 0; i < 8; ++i)
                #pragma unroll
                for (int j = 0; j < 8; ++j)
                    acc[i][j] += a[i] * b[j];
        }
        __syncthreads();
    }
    #pragma unroll
    for (int i = 0; i < 8; ++i) {
        size_t row = (size_t)(bm + ty*8 + i) * N + bn + tx*8;
        *(float4*)&C[row]     = make_float4(acc[i][0], acc[i][1], acc[i][2], acc[i][3]);
        *(float4*)&C[row + 4] = make_float4(acc[i][4], acc[i][5], acc[i][6], acc[i][7]);
    }
}

// ---------------------------------------------------------------------------
// RoPE helpers
// ---------------------------------------------------------------------------
__device__ __forceinline__ void rope_pair(float x1, float x2, int pos, int d,
                                          float& o1, float& o2)
{
    double invf = pow(10000.0, -((double)d) / 64.0);
    float ang = (float)pos * (float)invf;
    float sn, cs;
    sincosf(ang, &sn, &cs);
    o1 = x1 * cs - x2 * sn;
    o2 = x1 * sn + x2 * cs;
}

// Q: in-place rope on g_q ([s][h*128+d])
__global__ void rope_q_kernel(const int* __restrict__ positions)
{
    int idx = blockIdx.x * blockDim.x + threadIdx.x;   // NH*S*64
    int d = idx & 63;
    int s = (idx >> 6) & (S_ - 1);
    int h = idx >> 17;
    size_t base = (size_t)s * HID_ + h * HD_;
    float x1 = g_q[base + d], x2 = g_q[base + d + 64];
    float o1, o2;
    rope_pair(x1, x2, positions[s], d, o1, o2);
    g_q[base + d] = o1; g_q[base + d + 64] = o2;
}

// K: rope g_k[s][kv*128+d] -> kout[h][s][d] replicated across GRP_ heads
__global__ void rope_k_kernel(const int* __restrict__ positions,
                              float* __restrict__ kout)
{
    int idx = blockIdx.x * blockDim.x + threadIdx.x;   // NKV*S*64
    int d  = idx & 63;
    int s  = (idx >> 6) & (S_ - 1);
    int kv = idx >> 17;
    size_t src = (size_t)s * KVD_ + kv * HD_;
    float x1 = g_k[src + d], x2 = g_k[src + d + 64];
    float o1, o2;
    rope_pair(x1, x2, positions[s], d, o1, o2);
    #pragma unroll
    for (int g = 0; g < GRP_; ++g) {
        size_t dst = ((size_t)(kv * GRP_ + g) * S_ + s) * HD_;
        kout[dst + d] = o1; kout[dst + d + 64] = o2;
    }
}

// V: copy g_v[s][kv*128+d] -> vout[h][s][d] replicated across GRP_ heads
__global__ void copy_v_kernel(float* __restrict__ vout)
{
    int idx = blockIdx.x * blockDim.x + threadIdx.x;   // NKV*S*32 float4s
    int d4 = idx & 31;
    int s  = (idx >> 5) & (S_ - 1);
    int kv = idx >> 16;
    float4 v = *(const float4*)&g_v[(size_t)s * KVD_ + kv * HD_ + d4 * 4];
    #pragma unroll
    for (int g = 0; g < GRP_; ++g)
        *(float4*)&vout[((size_t)(kv * GRP_ + g) * S_ + s) * HD_ + d4 * 4] = v;
}

// ---------------------------------------------------------------------------
// Flash attention (fp32, causal): BQ=64, BK=64, HD=128.
// 256 threads: tx=tid&15, ty=tid>>4; 4x4 score tile, 4x8 O tile per thread.
// Reads K,V from d_out regions ([h][t][d], repeated); writes g_att.
// ---------------------------------------------------------------------------
#define QS 132      // padded smem stride for 128-wide tiles
#define PS 68       // padded stride for p tile
#define FLASH_SMEM ((3*64*QS + 64*PS) * 4)

__global__ __launch_bounds__(256, 1)
void flash_kernel(const float* __restrict__ kf, const float* __restrict__ vf,
                  float* __restrict__ att)
{
    extern __shared__ float sm[];
    float* qs = sm;
    float* ks = sm + 64*QS;
    float* vs = sm + 2*64*QS;
    float* ps = sm + 3*64*QS;

    const int tid = threadIdx.x;
    const int tx = tid & 15, ty = tid >> 4;
    const int qb = blockIdx.x, h = blockIdx.y;
    const int q0 = qb * 64;
    const float* kbase = kf + (size_t)h * S_ * HD_;
    const float* vbase = vf + (size_t)h * S_ * HD_;
    const float scale = 0.08838834764831845f;   // 1/sqrt(128)

    // load Q tile (64x128)
    #pragma unroll
    for (int q = 0; q < 8; ++q) {
        int slot = tid + q * 256;               // 0..2047 float4 slots
        int r = slot >> 5, d4 = (slot & 31) * 4;
        float4 v4 = *(const float4*)&g_q[(size_t)(q0 + r) * HID_ + h * HD_ + d4];
        qs[r*QS + d4  ] = v4.x; qs[r*QS + d4+1] = v4.y;
        qs[r*QS + d4+2] = v4.z; qs[r*QS + d4+3] = v4.w;
    }

    float o[4][8];
    float m_[4], l_[4];
    #pragma unroll
    for (int i = 0; i < 4; ++i) {
        m_[i] = -1e30f; l_[i] = 0.f;
        #pragma unroll
        for (int j = 0; j < 8; ++j) o[i][j] = 0.f;
    }

    for (int kt = 0; kt <= qb; ++kt) {
        __syncthreads();   // previous iteration done reading ks/vs/ps
        #pragma unroll
        for (int q = 0; q < 8; ++q) {
            int slot = tid + q * 256;
            int r = slot >> 5, d4 = (slot & 31) * 4;
            size_t goff = (size_t)(kt * 64 + r) * HD_ + d4;
            float4 kk = *(const float4*)&kbase[goff];
            ks[r*QS + d4  ] = kk.x; ks[r*QS + d4+1] = kk.y;
            ks[r*QS + d4+2] = kk.z; ks[r*QS + d4+3] = kk.w;
            float4 vv = *(const float4*)&vbase[goff];
            vs[r*QS + d4  ] = vv.x; vs[r*QS + d4+1] = vv.y;
            vs[r*QS + d4+2] = vv.z; vs[r*QS + d4+3] = vv.w;
        }
        __syncthreads();

        // scores 4x4
        float acc[4][4];
        #pragma unroll
        for (int i = 0; i < 4; ++i)
            #pragma unroll
            for (int j = 0; j < 4; ++j) acc[i][j] = 0.f;

        #pragma unroll 8
        for (int d4 = 0; d4 < 32; ++d4) {
            float4 qv[4], kk4[4];
            #pragma unroll
            for (int i = 0; i < 4; ++i)
                qv[i] = *(float4*)&qs[(ty*4 + i)*QS + d4*4];
            #pragma unroll
            for (int j = 0; j < 4; ++j)
                kk4[j] = *(float4*)&ks[(tx*4 + j)*QS + d4*4];
            #pragma unroll
            for (int i = 0; i < 4; ++i)
                #pragma unroll
                for (int j = 0; j < 4; ++j)
                    acc[i][j] += qv[i].x*kk4[j].x + qv[i].y*kk4[j].y
                               + qv[i].z*kk4[j].z + qv[i].w*kk4[j].w;
        }

        const bool diag = (kt == qb);
        float mx[4];
        #pragma unroll
        for (int i = 0; i < 4; ++i) {
            mx[i] = -1e30f;
            #pragma unroll
            for (int j = 0; j < 4; ++j) {
                float s_ = acc[i][j] * scale;
                if (diag && (tx*4 + j) > (ty*4 + i)) s_ = -1e30f;
                acc[i][j] = s_;
                mx[i] = fmaxf(mx[i], s_);
            }
        }
        #pragma unroll
        for (int off = 8; off; off >>= 1)
            #pragma unroll
            for (int i = 0; i < 4; ++i)
                mx[i] = fmaxf(mx[i], __shfl_xor_sync(0xffffffffu, mx[i], off));

        float rs[4], alpha[4];
        #pragma unroll
        for (int i = 0; i < 4; ++i) {
            float mn = fmaxf(m_[i], mx[i]);
            alpha[i] = __expf(m_[i] - mn);
            m_[i] = mn;
            float s0 = 0.f;
            #pragma unroll
            for (int j = 0; j < 4; ++j) {
                acc[i][j] = __expf(acc[i][j] - mn);
                s0 += acc[i][j];
            }
            rs[i] = s0;
        }
        #pragma unroll
        for (int off = 8; off; off >>= 1)
            #pragma unroll
            for (int i = 0; i < 4; ++i)
                rs[i] += __shfl_xor_sync(0xffffffffu, rs[i], off);
        #pragma unroll
        for (int i = 0; i < 4; ++i) {
            l_[i] = l_[i] * alpha[i] + rs[i];
            #pragma unroll
            for (int j = 0; j < 8; ++j) o[i][j] *= alpha[i];
            #pragma unroll
            for (int j = 0; j < 4; ++j)
                ps[(ty*4 + i)*PS + tx*4 + j] = acc[i][j];
        }
        __syncwarp();   // p rows only shared within the half-warp (same ty)

        // O += P @ V
        #pragma unroll 4
        for (int c = 0; c < 64; ++c) {
            float4 v0 = *(float4*)&vs[c*QS + tx*8];
            float4 v1 = *(float4*)&vs[c*QS + tx*8 + 4];
            #pragma unroll
            for (int i = 0; i < 4; ++i) {
                float p = ps[(ty*4 + i)*PS + c];
                o[i][0] += p*v0.x; o[i][1] += p*v0.y;
                o[i][2] += p*v0.z; o[i][3] += p*v0.w;
                o[i][4] += p*v1.x; o[i][5] += p*v1.y;
                o[i][6] += p*v1.z; o[i][7] += p*v1.w;
            }
        }
    }

    #pragma unroll
    for (int i = 0; i < 4; ++i) {
        float inv = 1.f / l_[i];
        size_t row = (size_t)(q0 + ty*4 + i) * HID_ + h * HD_ + tx*8;
        *(float4*)&att[row]     = make_float4(o[i][0]*inv, o[i][1]*inv,
                                              o[i][2]*inv, o[i][3]*inv);
        *(float4*)&att[row + 4] = make_float4(o[i][4]*inv, o[i][5]*inv,
                                              o[i][6]*inv, o[i][7]*inv);
    }
}

// ---------------------------------------------------------------------------
extern "C" void kernel_launch(void* const* d_in, const int* in_sizes, int n_in,
                              void* d_out, int out_size)
{
    const float* hs  = (const float*)d_in[0];
    const int*   pos = (const int*)  d_in[1];
    // d_in[2] = mask (causal -1e9): implemented analytically
    const float* Wq  = (const float*)d_in[3];
    const float* Wk  = (const float*)d_in[4];
    const float* Wv  = (const float*)d_in[5];
    const float* Wo  = (const float*)d_in[6];

    float* out  = (float*)d_out;                       // [S, HID]
    float* kout = out  + (size_t)S_ * HID_;            // [NH, S, HD] (repeated)
    float* vout = kout + (size_t)NH_ * S_ * HD_;       // [NH, S, HD] (repeated)

    float *qp, *kp, *vp, *ap;
    cudaGetSymbolAddress((void**)&qp, g_q);
    cudaGetSymbolAddress((void**)&kp, g_k);
    cudaGetSymbolAddress((void**)&vp, g_v);
    cudaGetSymbolAddress((void**)&ap, g_att);

    // projections
    sgemm128<<<dim3(HID_/128, S_/128), 256>>>(hs, Wq, qp, S_, HID_, HID_);
    sgemm128<<<dim3(KVD_/128, S_/128), 256>>>(hs, Wk, kp, S_, KVD_, HID_);
    sgemm128<<<dim3(KVD_/128, S_/128), 256>>>(hs, Wv, vp, S_, KVD_, HID_);

    // rope + layout (writes repeated K/V into d_out)
    rope_q_kernel<<<(NH_*S_*64)/256, 256>>>(pos);
    rope_k_kernel<<<(NKV_*S_*64)/256, 256>>>(pos, kout);
    copy_v_kernel<<<(NKV_*S_*32)/256, 256>>>(vout);

    // attention
    cudaFuncSetAttribute(flash_kernel,
                         cudaFuncAttributeMaxDynamicSharedMemorySize, FLASH_SMEM);
    flash_kernel<<<dim3(S_/64, NH_), 256, FLASH_SMEM>>>(kout, vout, ap);

    // output projection
    sgemm128<<<dim3(HID_/128, S_/128), 256>>>(ap, Wo, out, S_, HID_, HID_);
}

// round 4
// speedup vs baseline: 1.8274x; 1.8274x over previous
#include <cuda_runtime.h>
#include <cuda_bf16.h>
#include <math.h>
#include <stdint.h>

#define S_   2048
#define HID_ 2048
#define NH_  16
#define NKV_ 4
#define GRP_ (NH_/NKV_)   // 4
#define HD_  128
#define KVD_ (NKV_*HD_)   // 512

// ---------------------------------------------------------------------------
// scratch (allocation-free: __device__ globals)
// ---------------------------------------------------------------------------
__device__ float g_q  [S_*HID_];   // Q projection (fp32), roped in place
__device__ float g_k  [S_*KVD_];   // K projection pre-rope
__device__ float g_v  [S_*KVD_];   // V projection

__device__ __nv_bfloat16 g_hs_hi[S_*HID_],  g_hs_lo[S_*HID_];    // hidden [m][k]
__device__ __nv_bfloat16 g_wq_hi[HID_*HID_],g_wq_lo[HID_*HID_];  // [n][k]
__device__ __nv_bfloat16 g_wk_hi[KVD_*HID_],g_wk_lo[KVD_*HID_];
__device__ __nv_bfloat16 g_wv_hi[KVD_*HID_],g_wv_lo[KVD_*HID_];
__device__ __nv_bfloat16 g_wo_hi[HID_*HID_],g_wo_lo[HID_*HID_];
__device__ __nv_bfloat16 g_at_hi[S_*HID_],  g_at_lo[S_*HID_];    // attn out [m][k]

// ---------------------------------------------------------------------------
// mma.sync / ldmatrix / cp.async helpers (plain sm_103-safe PTX)
// ---------------------------------------------------------------------------
__device__ __forceinline__ uint32_t smem_to_u32(const void* p) {
    uint32_t a;
    asm("{ .reg .u64 t; cvta.to.shared.u64 t, %1; cvt.u32.u64 %0, t; }"
        : "=r"(a) : "l"(p));
    return a;
}
__device__ __forceinline__ void cp16(uint32_t dst, const void* src) {
    asm volatile("cp.async.cg.shared.global [%0], [%1], 16;" :: "r"(dst), "l"(src));
}
#define CP_COMMIT() asm volatile("cp.async.commit_group;" ::: "memory")
#define CP_WAIT(n)  asm volatile("cp.async.wait_group %0;" :: "n"(n) : "memory")

__device__ __forceinline__ void ldm_x4(uint32_t* r, uint32_t addr) {
    asm volatile("ldmatrix.sync.aligned.m8n8.x4.shared.b16 {%0,%1,%2,%3}, [%4];"
        : "=r"(r[0]), "=r"(r[1]), "=r"(r[2]), "=r"(r[3]) : "r"(addr));
}
__device__ __forceinline__ void ldm_x2(uint32_t* r, uint32_t addr) {
    asm volatile("ldmatrix.sync.aligned.m8n8.x2.shared.b16 {%0,%1}, [%2];"
        : "=r"(r[0]), "=r"(r[1]) : "r"(addr));
}
__device__ __forceinline__ void mma_bf16(float* c, const uint32_t* a, const uint32_t* b) {
    asm volatile("mma.sync.aligned.m16n8k16.row.col.f32.bf16.bf16.f32 "
        "{%0,%1,%2,%3}, {%4,%5,%6,%7}, {%8,%9}, {%0,%1,%2,%3};"
        : "+f"(c[0]), "+f"(c[1]), "+f"(c[2]), "+f"(c[3])
        : "r"(a[0]), "r"(a[1]), "r"(a[2]), "r"(a[3]), "r"(b[0]), "r"(b[1]));
}

// ---------------------------------------------------------------------------
// fp32 -> bf16 hi/lo split (no transpose), float4 granularity
// ---------------------------------------------------------------------------
__global__ void conv_split_kernel(const float* __restrict__ src,
                                  __nv_bfloat16* __restrict__ hi,
                                  __nv_bfloat16* __restrict__ lo)
{
    int i = blockIdx.x * 256 + threadIdx.x;
    float4 v = ((const float4*)src)[i];
    float f[4] = {v.x, v.y, v.z, v.w};
    union { uint2 u; __nv_bfloat16 b[4]; } H, L;
    #pragma unroll
    for (int j = 0; j < 4; ++j) {
        __nv_bfloat16 h = __float2bfloat16(f[j]);
        H.b[j] = h;
        L.b[j] = __float2bfloat16(f[j] - __bfloat162float(h));
    }
    ((uint2*)hi)[i] = H.u;
    ((uint2*)lo)[i] = L.u;
}

// fp32 W[Kd][Nd] -> bf16 hi/lo [Nd][Kd] (transpose)
__global__ void transpose_split_kernel(const float* __restrict__ W,
                                       __nv_bfloat16* __restrict__ hi,
                                       __nv_bfloat16* __restrict__ lo,
                                       int Kd, int Nd)
{
    __shared__ float t[32][33];
    int bn = blockIdx.x * 32;
    int bk = blockIdx.y * 32;
    int x = threadIdx.x, y = threadIdx.y;   // (32, 8)
    #pragma unroll
    for (int i = 0; i < 32; i += 8)
        t[y + i][x] = W[(size_t)(bk + y + i) * Nd + bn + x];
    __syncthreads();
    #pragma unroll
    for (int i = 0; i < 32; i += 8) {
        float v = t[x][y + i];
        __nv_bfloat16 h = __float2bfloat16(v);
        size_t o = (size_t)(bn + y + i) * Kd + bk + x;
        hi[o] = h;
        lo[o] = __float2bfloat16(v - __bfloat162float(h));
    }
}

// ---------------------------------------------------------------------------
// mma.sync GEMM body: C[128,128] fp32 tile = (Ahi+Alo) @ (Bhi+Blo)^T
// SMEM tiles: 128 rows x 32 cols bf16, padded row stride 40 elems (80 B).
// Order in each buffer: Ahi, Alo, Bhi, Blo (TILE_B bytes apart).
// ---------------------------------------------------------------------------
#define TILE_B   10240              // 128*80
#define BUF_B    (4*TILE_B)         // 40960
#define GEMM_SMEM (2*BUF_B)         // 81920

__device__ __forceinline__ void load_tile_async(uint32_t sdst,
                                                const __nv_bfloat16* g,
                                                int ldk, int tid)
{
    int r   = tid >> 2;       // 0..63
    int seg = tid & 3;        // 0..3 (16B segments)
    #pragma unroll
    for (int h = 0; h < 2; ++h) {
        int row = r + h * 64;
        cp16(sdst + row * 80 + seg * 16, g + (size_t)row * ldk + seg * 8);
    }
}

__device__ __forceinline__ void gemm_body(
    uint32_t sb, char* smp,
    const __nv_bfloat16* Ahi, const __nv_bfloat16* Alo,   // + bm*K
    const __nv_bfloat16* Bhi, const __nv_bfloat16* Blo,   // + bn*K
    float* C, int N, int K, int tid)                      // C + bm*N + bn
{
    const int lane = tid & 31, wid = tid >> 5;
    const int wm = wid & 1, wn = wid >> 1;    // warp tile: 64(m) x 32(n)

    float acc[4][4][4];
    #pragma unroll
    for (int mi = 0; mi < 4; ++mi)
        #pragma unroll
        for (int ni = 0; ni < 4; ++ni)
            #pragma unroll
            for (int q = 0; q < 4; ++q) acc[mi][ni][q] = 0.f;

    const int T = K / 32;
    // prologue: tile 0
    load_tile_async(sb,            Ahi, K, tid);
    load_tile_async(sb +   TILE_B, Alo, K, tid);
    load_tile_async(sb + 2*TILE_B, Bhi, K, tid);
    load_tile_async(sb + 3*TILE_B, Blo, K, tid);
    CP_COMMIT();

    const uint32_t a_lane_off = (uint32_t)((lane & 15) * 80 + (lane >> 4) * 16);
    const uint32_t b_lane_off = (uint32_t)((lane & 7) * 80 + ((lane >> 3) & 1) * 16);

    for (int kt = 0; kt < T; ++kt) {
        if (kt + 1 < T) {
            uint32_t nb = sb + ((kt + 1) & 1) * BUF_B;
            int k0 = (kt + 1) * 32;
            load_tile_async(nb,            Ahi + k0, K, tid);
            load_tile_async(nb +   TILE_B, Alo + k0, K, tid);
            load_tile_async(nb + 2*TILE_B, Bhi + k0, K, tid);
            load_tile_async(nb + 3*TILE_B, Blo + k0, K, tid);
            CP_COMMIT();
            CP_WAIT(1);
        } else {
            CP_WAIT(0);
        }
        __syncthreads();

        uint32_t buf = sb + (kt & 1) * BUF_B;
        #pragma unroll
        for (int ks = 0; ks < 2; ++ks) {
            uint32_t ah[4][4], al[4][4], bh[4][2], bl[4][2];
            uint32_t abase = buf + wm * (64 * 80) + a_lane_off + ks * 32;
            #pragma unroll
            for (int mi = 0; mi < 4; ++mi) {
                ldm_x4(ah[mi], abase + mi * (16 * 80));
                ldm_x4(al[mi], abase + TILE_B + mi * (16 * 80));
            }
            uint32_t bbase = buf + 2*TILE_B + wn * (32 * 80) + b_lane_off + ks * 32;
            #pragma unroll
            for (int ni = 0; ni < 4; ++ni) {
                ldm_x2(bh[ni], bbase + ni * (8 * 80));
                ldm_x2(bl[ni], bbase + TILE_B + ni * (8 * 80));
            }
            #pragma unroll
            for (int mi = 0; mi < 4; ++mi)
                #pragma unroll
                for (int ni = 0; ni < 4; ++ni) {
                    mma_bf16(acc[mi][ni], ah[mi], bh[ni]);
                    mma_bf16(acc[mi][ni], ah[mi], bl[ni]);
                    mma_bf16(acc[mi][ni], al[mi], bh[ni]);
                }
        }
        __syncthreads();
    }

    // epilogue
    #pragma unroll
    for (int mi = 0; mi < 4; ++mi) {
        int row = wm * 64 + mi * 16 + (lane >> 2);
        #pragma unroll
        for (int ni = 0; ni < 4; ++ni) {
            int col = wn * 32 + ni * 8 + (lane & 3) * 2;
            *(float2*)&C[(size_t)row * N + col] =
                make_float2(acc[mi][ni][0], acc[mi][ni][1]);
            *(float2*)&C[(size_t)(row + 8) * N + col] =
                make_float2(acc[mi][ni][2], acc[mi][ni][3]);
        }
    }
}

// fused QKV: blockIdx.x selects output (0..15 Q, 16..19 K, 20..23 V)
__global__ __launch_bounds__(256, 1)
void qkv_gemm_kernel(const __nv_bfloat16* __restrict__ Ahi,
                     const __nv_bfloat16* __restrict__ Alo,
                     const __nv_bfloat16* __restrict__ Wqh,
                     const __nv_bfloat16* __restrict__ Wql,
                     const __nv_bfloat16* __restrict__ Wkh,
                     const __nv_bfloat16* __restrict__ Wkl,
                     const __nv_bfloat16* __restrict__ Wvh,
                     const __nv_bfloat16* __restrict__ Wvl,
                     float* __restrict__ Cq, float* __restrict__ Ck,
                     float* __restrict__ Cv)
{
    extern __shared__ char smp[];
    uint32_t sb = smem_to_u32(smp);
    const int nb = blockIdx.x;
    const int bm = blockIdx.y * 128;
    const __nv_bfloat16 *Bh, *Bl;
    float* C;
    int N, bn;
    if (nb < 16)      { Bh = Wqh; Bl = Wql; C = Cq; N = HID_; bn = nb * 128; }
    else if (nb < 20) { Bh = Wkh; Bl = Wkl; C = Ck; N = KVD_; bn = (nb - 16) * 128; }
    else              { Bh = Wvh; Bl = Wvl; C = Cv; N = KVD_; bn = (nb - 20) * 128; }
    gemm_body(sb, smp,
              Ahi + (size_t)bm * HID_, Alo + (size_t)bm * HID_,
              Bh + (size_t)bn * HID_,  Bl + (size_t)bn * HID_,
              C + (size_t)bm * N + bn, N, HID_, threadIdx.x);
}

__global__ __launch_bounds__(256, 1)
void gemm_mma_kernel(const __nv_bfloat16* __restrict__ Ahi,
                     const __nv_bfloat16* __restrict__ Alo,
                     const __nv_bfloat16* __restrict__ Bhi,
                     const __nv_bfloat16* __restrict__ Blo,
                     float* __restrict__ C, int N, int K)
{
    extern __shared__ char smp[];
    uint32_t sb = smem_to_u32(smp);
    const int bm = blockIdx.y * 128, bn = blockIdx.x * 128;
    gemm_body(sb, smp,
              Ahi + (size_t)bm * K, Alo + (size_t)bm * K,
              Bhi + (size_t)bn * K, Blo + (size_t)bn * K,
              C + (size_t)bm * N + bn, N, K, threadIdx.x);
}

// ---------------------------------------------------------------------------
// RoPE (pure fp32 — no FP64)
// ---------------------------------------------------------------------------
__device__ __forceinline__ void rope_pair(float x1, float x2, int pos, int d,
                                          float& o1, float& o2)
{
    float inv = exp2f((float)d * (-13.287712379549449f / 64.0f));
    float ang = (float)pos * inv;
    float sn, cs;
    sincosf(ang, &sn, &cs);
    o1 = x1 * cs - x2 * sn;
    o2 = x1 * sn + x2 * cs;
}

__global__ void rope_q_kernel(const int* __restrict__ positions)
{
    int idx = blockIdx.x * blockDim.x + threadIdx.x;   // NH*S*64
    int d = idx & 63;
    int s = (idx >> 6) & (S_ - 1);
    int h = idx >> 17;
    size_t base = (size_t)s * HID_ + h * HD_;
    float x1 = g_q[base + d], x2 = g_q[base + d + 64];
    float o1, o2;
    rope_pair(x1, x2, positions[s], d, o1, o2);
    g_q[base + d] = o1; g_q[base + d + 64] = o2;
}

__global__ void rope_k_kernel(const int* __restrict__ positions,
                              float* __restrict__ kout)
{
    int idx = blockIdx.x * blockDim.x + threadIdx.x;   // NKV*S*64
    int d  = idx & 63;
    int s  = (idx >> 6) & (S_ - 1);
    int kv = idx >> 17;
    size_t src = (size_t)s * KVD_ + kv * HD_;
    float x1 = g_k[src + d], x2 = g_k[src + d + 64];
    float o1, o2;
    rope_pair(x1, x2, positions[s], d, o1, o2);
    #pragma unroll
    for (int g = 0; g < GRP_; ++g) {
        size_t dst = ((size_t)(kv * GRP_ + g) * S_ + s) * HD_;
        kout[dst + d] = o1; kout[dst + d + 64] = o2;
    }
}

__global__ void copy_v_kernel(float* __restrict__ vout)
{
    int idx = blockIdx.x * blockDim.x + threadIdx.x;   // NKV*S*32 float4s
    int d4 = idx & 31;
    int s  = (idx >> 5) & (S_ - 1);
    int kv = idx >> 16;
    float4 v = *(const float4*)&g_v[(size_t)s * KVD_ + kv * HD_ + d4 * 4];
    #pragma unroll
    for (int g = 0; g < GRP_; ++g)
        *(float4*)&vout[((size_t)(kv * GRP_ + g) * S_ + s) * HD_ + d4 * 4] = v;
}

// ---------------------------------------------------------------------------
// Flash attention (fp32, causal): BQ=64, BK=64, HD=128. Epilogue -> bf16 hi/lo.
// ---------------------------------------------------------------------------
#define QS 132
#define PS 68
#define FLASH_SMEM ((3*64*QS + 64*PS) * 4)

__global__ __launch_bounds__(256, 1)
void flash_kernel(const float* __restrict__ kf, const float* __restrict__ vf,
                  __nv_bfloat16* __restrict__ att_hi,
                  __nv_bfloat16* __restrict__ att_lo)
{
    extern __shared__ float smf[];
    float* qs = smf;
    float* ks = smf + 64*QS;
    float* vs = smf + 2*64*QS;
    float* ps = smf + 3*64*QS;

    const int tid = threadIdx.x;
    const int tx = tid & 15, ty = tid >> 4;
    const int qb = blockIdx.x, h = blockIdx.y;
    const int q0 = qb * 64;
    const float* kbase = kf + (size_t)h * S_ * HD_;
    const float* vbase = vf + (size_t)h * S_ * HD_;
    const float scale = 0.08838834764831845f;

    #pragma unroll
    for (int q = 0; q < 8; ++q) {
        int slot = tid + q * 256;
        int r = slot >> 5, d4 = (slot & 31) * 4;
        float4 v4 = *(const float4*)&g_q[(size_t)(q0 + r) * HID_ + h * HD_ + d4];
        qs[r*QS + d4  ] = v4.x; qs[r*QS + d4+1] = v4.y;
        qs[r*QS + d4+2] = v4.z; qs[r*QS + d4+3] = v4.w;
    }

    float o[4][8];
    float m_[4], l_[4];
    #pragma unroll
    for (int i = 0; i < 4; ++i) {
        m_[i] = -1e30f; l_[i] = 0.f;
        #pragma unroll
        for (int j = 0; j < 8; ++j) o[i][j] = 0.f;
    }

    for (int kt = 0; kt <= qb; ++kt) {
        __syncthreads();
        #pragma unroll
        for (int q = 0; q < 8; ++q) {
            int slot = tid + q * 256;
            int r = slot >> 5, d4 = (slot & 31) * 4;
            size_t goff = (size_t)(kt * 64 + r) * HD_ + d4;
            float4 kk = *(const float4*)&kbase[goff];
            ks[r*QS + d4  ] = kk.x; ks[r*QS + d4+1] = kk.y;
            ks[r*QS + d4+2] = kk.z; ks[r*QS + d4+3] = kk.w;
            float4 vv = *(const float4*)&vbase[goff];
            vs[r*QS + d4  ] = vv.x; vs[r*QS + d4+1] = vv.y;
            vs[r*QS + d4+2] = vv.z; vs[r*QS + d4+3] = vv.w;
        }
        __syncthreads();

        float acc[4][4];
        #pragma unroll
        for (int i = 0; i < 4; ++i)
            #pragma unroll
            for (int j = 0; j < 4; ++j) acc[i][j] = 0.f;

        #pragma unroll 8
        for (int d4 = 0; d4 < 32; ++d4) {
            float4 qv[4], kk4[4];
            #pragma unroll
            for (int i = 0; i < 4; ++i)
                qv[i] = *(float4*)&qs[(ty*4 + i)*QS + d4*4];
            #pragma unroll
            for (int j = 0; j < 4; ++j)
                kk4[j] = *(float4*)&ks[(tx*4 + j)*QS + d4*4];
            #pragma unroll
            for (int i = 0; i < 4; ++i)
                #pragma unroll
                for (int j = 0; j < 4; ++j)
                    acc[i][j] += qv[i].x*kk4[j].x + qv[i].y*kk4[j].y
                               + qv[i].z*kk4[j].z + qv[i].w*kk4[j].w;
        }

        const bool diag = (kt == qb);
        float mx[4];
        #pragma unroll
        for (int i = 0; i < 4; ++i) {
            mx[i] = -1e30f;
            #pragma unroll
            for (int j = 0; j < 4; ++j) {
                float s_ = acc[i][j] * scale;
                if (diag && (tx*4 + j) > (ty*4 + i)) s_ = -1e30f;
                acc[i][j] = s_;
                mx[i] = fmaxf(mx[i], s_);
            }
        }
        #pragma unroll
        for (int off = 8; off; off >>= 1)
            #pragma unroll
            for (int i = 0; i < 4; ++i)
                mx[i] = fmaxf(mx[i], __shfl_xor_sync(0xffffffffu, mx[i], off));

        float rs[4], alpha[4];
        #pragma unroll
        for (int i = 0; i < 4; ++i) {
            float mn = fmaxf(m_[i], mx[i]);
            alpha[i] = __expf(m_[i] - mn);
            m_[i] = mn;
            float s0 = 0.f;
            #pragma unroll
            for (int j = 0; j < 4; ++j) {
                acc[i][j] = __expf(acc[i][j] - mn);
                s0 += acc[i][j];
            }
            rs[i] = s0;
        }
        #pragma unroll
        for (int off = 8; off; off >>= 1)
            #pragma unroll
            for (int i = 0; i < 4; ++i)
                rs[i] += __shfl_xor_sync(0xffffffffu, rs[i], off);
        #pragma unroll
        for (int i = 0; i < 4; ++i) {
            l_[i] = l_[i] * alpha[i] + rs[i];
            #pragma unroll
            for (int j = 0; j < 8; ++j) o[i][j] *= alpha[i];
            #pragma unroll
            for (int j = 0; j < 4; ++j)
                ps[(ty*4 + i)*PS + tx*4 + j] = acc[i][j];
        }
        __syncwarp();

        #pragma unroll 4
        for (int c = 0; c < 64; ++c) {
            float4 v0 = *(float4*)&vs[c*QS + tx*8];
            float4 v1 = *(float4*)&vs[c*QS + tx*8 + 4];
            #pragma unroll
            for (int i = 0; i < 4; ++i) {
                float p = ps[(ty*4 + i)*PS + c];
                o[i][0] += p*v0.x; o[i][1] += p*v0.y;
                o[i][2] += p*v0.z; o[i][3] += p*v0.w;
                o[i][4] += p*v1.x; o[i][5] += p*v1.y;
                o[i][6] += p*v1.z; o[i][7] += p*v1.w;
            }
        }
    }

    #pragma unroll
    for (int i = 0; i < 4; ++i) {
        float inv = 1.f / l_[i];
        union { uint4 u; __nv_bfloat16 b[8]; } H, L;
        #pragma unroll
        for (int j = 0; j < 8; ++j) {
            float v = o[i][j] * inv;
            __nv_bfloat16 bh = __float2bfloat16(v);
            H.b[j] = bh;
            L.b[j] = __float2bfloat16(v - __bfloat162float(bh));
        }
        size_t row = (size_t)(q0 + ty*4 + i) * HID_ + h * HD_ + tx*8;
        *(uint4*)&att_hi[row] = H.u;
        *(uint4*)&att_lo[row] = L.u;
    }
}

// ---------------------------------------------------------------------------
extern "C" void kernel_launch(void* const* d_in, const int* in_sizes, int n_in,
                              void* d_out, int out_size)
{
    const float* hs  = (const float*)d_in[0];
    const int*   pos = (const int*)  d_in[1];
    const float* Wq  = (const float*)d_in[3];
    const float* Wk  = (const float*)d_in[4];
    const float* Wv  = (const float*)d_in[5];
    const float* Wo  = (const float*)d_in[6];

    float* out  = (float*)d_out;                       // [S, HID]
    float* kout = out  + (size_t)S_ * HID_;            // [NH, S, HD] (repeated)
    float* vout = kout + (size_t)NH_ * S_ * HD_;       // [NH, S, HD] (repeated)

    float *qp, *kp, *vp;
    cudaGetSymbolAddress((void**)&qp, g_q);
    cudaGetSymbolAddress((void**)&kp, g_k);
    cudaGetSymbolAddress((void**)&vp, g_v);
    __nv_bfloat16 *hsh, *hsl, *wqh, *wql, *wkh, *wkl, *wvh, *wvl, *woh, *wol, *ath, *atl;
    cudaGetSymbolAddress((void**)&hsh, g_hs_hi); cudaGetSymbolAddress((void**)&hsl, g_hs_lo);
    cudaGetSymbolAddress((void**)&wqh, g_wq_hi); cudaGetSymbolAddress((void**)&wql, g_wq_lo);
    cudaGetSymbolAddress((void**)&wkh, g_wk_hi); cudaGetSymbolAddress((void**)&wkl, g_wk_lo);
    cudaGetSymbolAddress((void**)&wvh, g_wv_hi); cudaGetSymbolAddress((void**)&wvl, g_wv_lo);
    cudaGetSymbolAddress((void**)&woh, g_wo_hi); cudaGetSymbolAddress((void**)&wol, g_wo_lo);
    cudaGetSymbolAddress((void**)&ath, g_at_hi); cudaGetSymbolAddress((void**)&atl, g_at_lo);

    cudaFuncSetAttribute(qkv_gemm_kernel,
                         cudaFuncAttributeMaxDynamicSharedMemorySize, GEMM_SMEM);
    cudaFuncSetAttribute(gemm_mma_kernel,
                         cudaFuncAttributeMaxDynamicSharedMemorySize, GEMM_SMEM);
    cudaFuncSetAttribute(flash_kernel,
                         cudaFuncAttributeMaxDynamicSharedMemorySize, FLASH_SMEM);

    // input conversions
    conv_split_kernel<<<(S_*HID_/4)/256, 256>>>(hs, hsh, hsl);
    transpose_split_kernel<<<dim3(HID_/32, HID_/32), dim3(32,8)>>>(Wq, wqh, wql, HID_, HID_);
    transpose_split_kernel<<<dim3(KVD_/32, HID_/32), dim3(32,8)>>>(Wk, wkh, wkl, HID_, KVD_);
    transpose_split_kernel<<<dim3(KVD_/32, HID_/32), dim3(32,8)>>>(Wv, wvh, wvl, HID_, KVD_);
    transpose_split_kernel<<<dim3(HID_/32, HID_/32), dim3(32,8)>>>(Wo, woh, wol, HID_, HID_);

    // fused QKV projection (tensor core, bf16x3)
    qkv_gemm_kernel<<<dim3(24, S_/128), 256, GEMM_SMEM>>>(
        hsh, hsl, wqh, wql, wkh, wkl, wvh, wvl, qp, kp, vp);

    // rope + layout (writes repeated K/V into d_out)
    rope_q_kernel<<<(NH_*S_*64)/256, 256>>>(pos);
    rope_k_kernel<<<(NKV_*S_*64)/256, 256>>>(pos, kout);
    copy_v_kernel<<<(NKV_*S_*32)/256, 256>>>(vout);

    // attention (fp32) -> bf16 hi/lo
    flash_kernel<<<dim3(S_/64, NH_), 256, FLASH_SMEM>>>(kout, vout, ath, atl);

    // output projection (tensor core, bf16x3)
    gemm_mma_kernel<<<dim3(HID_/128, S_/128), 256, GEMM_SMEM>>>(
        ath, atl, woh, wol, out, HID_, HID_);
}

// round 5
// speedup vs baseline: 4.0535x; 2.2182x over previous
#include <cuda_runtime.h>
#include <cuda_bf16.h>
#include <math.h>
#include <stdint.h>

#define S_   2048
#define HID_ 2048
#define NH_  16
#define NKV_ 4
#define GRP_ (NH_/NKV_)   // 4
#define HD_  128
#define KVD_ (NKV_*HD_)   // 512

// scale * log2(e), folded into Q at rope time
#define SCL_LOG2E 0.12751744f

// ---------------------------------------------------------------------------
// scratch (allocation-free: __device__ globals)
// ---------------------------------------------------------------------------
__device__ float g_q  [S_*HID_];   // Q projection (fp32)
__device__ float g_k  [S_*KVD_];   // K projection pre-rope
__device__ float g_v  [S_*KVD_];   // V projection

__device__ __nv_bfloat16 g_hs_hi[S_*HID_],  g_hs_lo[S_*HID_];    // hidden [m][k]
__device__ __nv_bfloat16 g_wq_hi[HID_*HID_],g_wq_lo[HID_*HID_];  // [n][k]
__device__ __nv_bfloat16 g_wk_hi[KVD_*HID_],g_wk_lo[KVD_*HID_];
__device__ __nv_bfloat16 g_wv_hi[KVD_*HID_],g_wv_lo[KVD_*HID_];
__device__ __nv_bfloat16 g_wo_hi[HID_*HID_],g_wo_lo[HID_*HID_];
__device__ __nv_bfloat16 g_at_hi[S_*HID_],  g_at_lo[S_*HID_];    // attn out [m][k]

__device__ __nv_bfloat16 g_qb_hi[S_*HID_],  g_qb_lo[S_*HID_];    // roped Q*scl [s][h*128+d]
__device__ __nv_bfloat16 g_kb_hi[NKV_*S_*HD_], g_kb_lo[NKV_*S_*HD_]; // [kv][s][d]
__device__ __nv_bfloat16 g_vb_hi[NKV_*S_*HD_], g_vb_lo[NKV_*S_*HD_];

// ---------------------------------------------------------------------------
// PTX helpers (plain sm_103-safe)
// ---------------------------------------------------------------------------
__device__ __forceinline__ uint32_t smem_to_u32(const void* p) {
    uint32_t a;
    asm("{ .reg .u64 t; cvta.to.shared.u64 t, %1; cvt.u32.u64 %0, t; }"
        : "=r"(a) : "l"(p));
    return a;
}
__device__ __forceinline__ void cp16(uint32_t dst, const void* src) {
    asm volatile("cp.async.cg.shared.global [%0], [%1], 16;" :: "r"(dst), "l"(src));
}
#define CP_COMMIT() asm volatile("cp.async.commit_group;" ::: "memory")
#define CP_WAIT(n)  asm volatile("cp.async.wait_group %0;" :: "n"(n) : "memory")

__device__ __forceinline__ void ldm_x4(uint32_t* r, uint32_t addr) {
    asm volatile("ldmatrix.sync.aligned.m8n8.x4.shared.b16 {%0,%1,%2,%3}, [%4];"
        : "=r"(r[0]), "=r"(r[1]), "=r"(r[2]), "=r"(r[3]) : "r"(addr));
}
__device__ __forceinline__ void ldm_x2(uint32_t* r, uint32_t addr) {
    asm volatile("ldmatrix.sync.aligned.m8n8.x2.shared.b16 {%0,%1}, [%2];"
        : "=r"(r[0]), "=r"(r[1]) : "r"(addr));
}
__device__ __forceinline__ void ldm_x2t(uint32_t* r, uint32_t addr) {
    asm volatile("ldmatrix.sync.aligned.m8n8.x2.trans.shared.b16 {%0,%1}, [%2];"
        : "=r"(r[0]), "=r"(r[1]) : "r"(addr));
}
__device__ __forceinline__ void mma_bf16(float* c, const uint32_t* a, const uint32_t* b) {
    asm volatile("mma.sync.aligned.m16n8k16.row.col.f32.bf16.bf16.f32 "
        "{%0,%1,%2,%3}, {%4,%5,%6,%7}, {%8,%9}, {%0,%1,%2,%3};"
        : "+f"(c[0]), "+f"(c[1]), "+f"(c[2]), "+f"(c[3])
        : "r"(a[0]), "r"(a[1]), "r"(a[2]), "r"(a[3]), "r"(b[0]), "r"(b[1]));
}

// pack x (low half) and y (high half) into bf16x2, plus residual pack
__device__ __forceinline__ void pack_hilo(float x, float y, uint32_t& hi, uint32_t& lo) {
    uint32_t h;
    asm("cvt.rn.bf16x2.f32 %0, %1, %2;" : "=r"(h) : "f"(y), "f"(x));
    float hx = __uint_as_float(h << 16);
    float hy = __uint_as_float(h & 0xffff0000u);
    float lx = x - hx, ly = y - hy;
    uint32_t l;
    asm("cvt.rn.bf16x2.f32 %0, %1, %2;" : "=r"(l) : "f"(ly), "f"(lx));
    hi = h; lo = l;
}

// fast 2^x on FMA pipe (x <= ~0, clamped); ~1e-8 rel err
__device__ __forceinline__ float fexp2(float x) {
    x = fmaxf(x, -126.0f);
    int e = __float2int_rn(x);
    float f = x - (float)e;
    float p = 0.0018775767f;
    p = fmaf(p, f, 0.0089893397f);
    p = fmaf(p, f, 0.0558040221f);
    p = fmaf(p, f, 0.2402264923f);
    p = fmaf(p, f, 0.6931471825f);
    p = fmaf(p, f, 1.0f);
    return __int_as_float(__float_as_int(p) + (e << 23));
}

// ---------------------------------------------------------------------------
// fp32 -> bf16 hi/lo split (no transpose), float4 granularity
// ---------------------------------------------------------------------------
__global__ void conv_split_kernel(const float* __restrict__ src,
                                  __nv_bfloat16* __restrict__ hi,
                                  __nv_bfloat16* __restrict__ lo)
{
    int i = blockIdx.x * 256 + threadIdx.x;
    float4 v = ((const float4*)src)[i];
    float f[4] = {v.x, v.y, v.z, v.w};
    union { uint2 u; __nv_bfloat16 b[4]; } H, L;
    #pragma unroll
    for (int j = 0; j < 4; ++j) {
        __nv_bfloat16 h = __float2bfloat16(f[j]);
        H.b[j] = h;
        L.b[j] = __float2bfloat16(f[j] - __bfloat162float(h));
    }
    ((uint2*)hi)[i] = H.u;
    ((uint2*)lo)[i] = L.u;
}

// fp32 W[Kd][Nd] -> bf16 hi/lo [Nd][Kd] (transpose)
__global__ void transpose_split_kernel(const float* __restrict__ W,
                                       __nv_bfloat16* __restrict__ hi,
                                       __nv_bfloat16* __restrict__ lo,
                                       int Kd, int Nd)
{
    __shared__ float t[32][33];
    int bn = blockIdx.x * 32;
    int bk = blockIdx.y * 32;
    int x = threadIdx.x, y = threadIdx.y;   // (32, 8)
    #pragma unroll
    for (int i = 0; i < 32; i += 8)
        t[y + i][x] = W[(size_t)(bk + y + i) * Nd + bn + x];
    __syncthreads();
    #pragma unroll
    for (int i = 0; i < 32; i += 8) {
        float v = t[x][y + i];
        __nv_bfloat16 h = __float2bfloat16(v);
        size_t o = (size_t)(bn + y + i) * Kd + bk + x;
        hi[o] = h;
        lo[o] = __float2bfloat16(v - __bfloat162float(h));
    }
}

// ---------------------------------------------------------------------------
// mma.sync GEMM body: C[128,128] fp32 tile = (Ahi+Alo) @ (Bhi+Blo)^T
// ---------------------------------------------------------------------------
#define TILE_B   10240              // 128*80
#define BUF_B    (4*TILE_B)         // 40960
#define GEMM_SMEM (2*BUF_B)         // 81920

__device__ __forceinline__ void load_tile_async(uint32_t sdst,
                                                const __nv_bfloat16* g,
                                                int ldk, int tid)
{
    int r   = tid >> 2;
    int seg = tid & 3;
    #pragma unroll
    for (int h = 0; h < 2; ++h) {
        int row = r + h * 64;
        cp16(sdst + row * 80 + seg * 16, g + (size_t)row * ldk + seg * 8);
    }
}

__device__ __forceinline__ void gemm_body(
    uint32_t sb,
    const __nv_bfloat16* Ahi, const __nv_bfloat16* Alo,
    const __nv_bfloat16* Bhi, const __nv_bfloat16* Blo,
    float* C, int N, int K, int tid)
{
    const int lane = tid & 31, wid = tid >> 5;
    const int wm = wid & 1, wn = wid >> 1;

    float acc[4][4][4];
    #pragma unroll
    for (int mi = 0; mi < 4; ++mi)
        #pragma unroll
        for (int ni = 0; ni < 4; ++ni)
            #pragma unroll
            for (int q = 0; q < 4; ++q) acc[mi][ni][q] = 0.f;

    const int T = K / 32;
    load_tile_async(sb,            Ahi, K, tid);
    load_tile_async(sb +   TILE_B, Alo, K, tid);
    load_tile_async(sb + 2*TILE_B, Bhi, K, tid);
    load_tile_async(sb + 3*TILE_B, Blo, K, tid);
    CP_COMMIT();

    const uint32_t a_lane_off = (uint32_t)((lane & 15) * 80 + (lane >> 4) * 16);
    const uint32_t b_lane_off = (uint32_t)((lane & 7) * 80 + ((lane >> 3) & 1) * 16);

    for (int kt = 0; kt < T; ++kt) {
        if (kt + 1 < T) {
            uint32_t nb = sb + ((kt + 1) & 1) * BUF_B;
            int k0 = (kt + 1) * 32;
            load_tile_async(nb,            Ahi + k0, K, tid);
            load_tile_async(nb +   TILE_B, Alo + k0, K, tid);
            load_tile_async(nb + 2*TILE_B, Bhi + k0, K, tid);
            load_tile_async(nb + 3*TILE_B, Blo + k0, K, tid);
            CP_COMMIT();
            CP_WAIT(1);
        } else {
            CP_WAIT(0);
        }
        __syncthreads();

        uint32_t buf = sb + (kt & 1) * BUF_B;
        #pragma unroll
        for (int ks = 0; ks < 2; ++ks) {
            uint32_t ah[4][4], al[4][4], bh[4][2], bl[4][2];
            uint32_t abase = buf + wm * (64 * 80) + a_lane_off + ks * 32;
            #pragma unroll
            for (int mi = 0; mi < 4; ++mi) {
                ldm_x4(ah[mi], abase + mi * (16 * 80));
                ldm_x4(al[mi], abase + TILE_B + mi * (16 * 80));
            }
            uint32_t bbase = buf + 2*TILE_B + wn * (32 * 80) + b_lane_off + ks * 32;
            #pragma unroll
            for (int ni = 0; ni < 4; ++ni) {
                ldm_x2(bh[ni], bbase + ni * (8 * 80));
                ldm_x2(bl[ni], bbase + TILE_B + ni * (8 * 80));
            }
            #pragma unroll
            for (int mi = 0; mi < 4; ++mi)
                #pragma unroll
                for (int ni = 0; ni < 4; ++ni) {
                    mma_bf16(acc[mi][ni], ah[mi], bh[ni]);
                    mma_bf16(acc[mi][ni], ah[mi], bl[ni]);
                    mma_bf16(acc[mi][ni], al[mi], bh[ni]);
                }
        }
        __syncthreads();
    }

    #pragma unroll
    for (int mi = 0; mi < 4; ++mi) {
        int row = wm * 64 + mi * 16 + (lane >> 2);
        #pragma unroll
        for (int ni = 0; ni < 4; ++ni) {
            int col = wn * 32 + ni * 8 + (lane & 3) * 2;
            *(float2*)&C[(size_t)row * N + col] =
                make_float2(acc[mi][ni][0], acc[mi][ni][1]);
            *(float2*)&C[(size_t)(row + 8) * N + col] =
                make_float2(acc[mi][ni][2], acc[mi][ni][3]);
        }
    }
}

__global__ __launch_bounds__(256, 1)
void qkv_gemm_kernel(const __nv_bfloat16* __restrict__ Ahi,
                     const __nv_bfloat16* __restrict__ Alo,
                     const __nv_bfloat16* __restrict__ Wqh,
                     const __nv_bfloat16* __restrict__ Wql,
                     const __nv_bfloat16* __restrict__ Wkh,
                     const __nv_bfloat16* __restrict__ Wkl,
                     const __nv_bfloat16* __restrict__ Wvh,
                     const __nv_bfloat16* __restrict__ Wvl,
                     float* __restrict__ Cq, float* __restrict__ Ck,
                     float* __restrict__ Cv)
{
    extern __shared__ char smp[];
    uint32_t sb = smem_to_u32(smp);
    const int nb = blockIdx.x;
    const int bm = blockIdx.y * 128;
    const __nv_bfloat16 *Bh, *Bl;
    float* C;
    int N, bn;
    if (nb < 16)      { Bh = Wqh; Bl = Wql; C = Cq; N = HID_; bn = nb * 128; }
    else if (nb < 20) { Bh = Wkh; Bl = Wkl; C = Ck; N = KVD_; bn = (nb - 16) * 128; }
    else              { Bh = Wvh; Bl = Wvl; C = Cv; N = KVD_; bn = (nb - 20) * 128; }
    gemm_body(sb,
              Ahi + (size_t)bm * HID_, Alo + (size_t)bm * HID_,
              Bh + (size_t)bn * HID_,  Bl + (size_t)bn * HID_,
              C + (size_t)bm * N + bn, N, HID_, threadIdx.x);
}

__global__ __launch_bounds__(256, 1)
void gemm_mma_kernel(const __nv_bfloat16* __restrict__ Ahi,
                     const __nv_bfloat16* __restrict__ Alo,
                     const __nv_bfloat16* __restrict__ Bhi,
                     const __nv_bfloat16* __restrict__ Blo,
                     float* __restrict__ C, int N, int K)
{
    extern __shared__ char smp[];
    uint32_t sb = smem_to_u32(smp);
    const int bm = blockIdx.y * 128, bn = blockIdx.x * 128;
    gemm_body(sb,
              Ahi + (size_t)bm * K, Alo + (size_t)bm * K,
              Bhi + (size_t)bn * K, Blo + (size_t)bn * K,
              C + (size_t)bm * N + bn, N, K, threadIdx.x);
}

// ---------------------------------------------------------------------------
// RoPE (pure fp32)
// ---------------------------------------------------------------------------
__device__ __forceinline__ void rope_pair(float x1, float x2, int pos, int d,
                                          float& o1, float& o2)
{
    float inv = exp2f((float)d * (-13.287712379549449f / 64.0f));
    float ang = (float)pos * inv;
    float sn, cs;
    sincosf(ang, &sn, &cs);
    o1 = x1 * cs - x2 * sn;
    o2 = x1 * sn + x2 * cs;
}

__device__ __forceinline__ void split_bf16(float v, __nv_bfloat16* hi, __nv_bfloat16* lo) {
    __nv_bfloat16 h = __float2bfloat16(v);
    *hi = h;
    *lo = __float2bfloat16(v - __bfloat162float(h));
}

// Q: rope + scale(SCL_LOG2E), write bf16 hi/lo [s][h*128+d]
__global__ void rope_q_kernel(const int* __restrict__ positions,
                              __nv_bfloat16* __restrict__ qh,
                              __nv_bfloat16* __restrict__ ql)
{
    int idx = blockIdx.x * blockDim.x + threadIdx.x;   // NH*S*64
    int d = idx & 63;
    int s = (idx >> 6) & (S_ - 1);
    int h = idx >> 17;
    size_t base = (size_t)s * HID_ + h * HD_;
    float x1 = g_q[base + d], x2 = g_q[base + d + 64];
    float o1, o2;
    rope_pair(x1, x2, positions[s], d, o1, o2);
    o1 *= SCL_LOG2E; o2 *= SCL_LOG2E;
    split_bf16(o1, &qh[base + d],      &ql[base + d]);
    split_bf16(o2, &qh[base + d + 64], &ql[base + d + 64]);
}

// K: rope; fp32 repeated -> kout[h][s][d]; bf16 hi/lo compact [kv][s][d]
__global__ void rope_k_kernel(const int* __restrict__ positions,
                              float* __restrict__ kout,
                              __nv_bfloat16* __restrict__ kbh,
                              __nv_bfloat16* __restrict__ kbl)
{
    int idx = blockIdx.x * blockDim.x + threadIdx.x;   // NKV*S*64
    int d  = idx & 63;
    int s  = (idx >> 6) & (S_ - 1);
    int kv = idx >> 17;
    size_t src = (size_t)s * KVD_ + kv * HD_;
    float x1 = g_k[src + d], x2 = g_k[src + d + 64];
    float o1, o2;
    rope_pair(x1, x2, positions[s], d, o1, o2);
    #pragma unroll
    for (int g = 0; g < GRP_; ++g) {
        size_t dst = ((size_t)(kv * GRP_ + g) * S_ + s) * HD_;
        kout[dst + d] = o1; kout[dst + d + 64] = o2;
    }
    size_t cb = ((size_t)kv * S_ + s) * HD_;
    split_bf16(o1, &kbh[cb + d],      &kbl[cb + d]);
    split_bf16(o2, &kbh[cb + d + 64], &kbl[cb + d + 64]);
}

// V: fp32 repeated -> vout; bf16 hi/lo compact
__global__ void copy_v_kernel(float* __restrict__ vout,
                              __nv_bfloat16* __restrict__ vbh,
                              __nv_bfloat16* __restrict__ vbl)
{
    int idx = blockIdx.x * blockDim.x + threadIdx.x;   // NKV*S*32 float4s
    int d4 = idx & 31;
    int s  = (idx >> 5) & (S_ - 1);
    int kv = idx >> 16;
    float4 v = *(const float4*)&g_v[(size_t)s * KVD_ + kv * HD_ + d4 * 4];
    #pragma unroll
    for (int g = 0; g < GRP_; ++g)
        *(float4*)&vout[((size_t)(kv * GRP_ + g) * S_ + s) * HD_ + d4 * 4] = v;
    size_t cb = ((size_t)kv * S_ + s) * HD_ + d4 * 4;
    float f[4] = {v.x, v.y, v.z, v.w};
    union { uint2 u; __nv_bfloat16 b[4]; } H, L;
    #pragma unroll
    for (int j = 0; j < 4; ++j) {
        __nv_bfloat16 h = __float2bfloat16(f[j]);
        H.b[j] = h;
        L.b[j] = __float2bfloat16(f[j] - __bfloat162float(h));
    }
    *(uint2*)&vbh[cb] = H.u;
    *(uint2*)&vbl[cb] = L.u;
}

// ---------------------------------------------------------------------------
// Tensor-core flash attention: BQ=128, BK=64, HD=128, 8 warps.
// Q pre-scaled by scale*log2e; softmax in base-2 via fexp2 (FMA pipe).
// ---------------------------------------------------------------------------
#define FSTR  272                   // bytes per smem row (256 + 16 pad)
#define FQ_B  (128*FSTR)            // 34816
#define FKV_B (64*FSTR)             // 17408
#define FLASH_SMEM (2*FQ_B + 8*FKV_B)  // 208896

__global__ __launch_bounds__(256, 1)
void flash_tc_kernel(const __nv_bfloat16* __restrict__ qhp,
                     const __nv_bfloat16* __restrict__ qlp,
                     const __nv_bfloat16* __restrict__ khp,
                     const __nv_bfloat16* __restrict__ klp,
                     const __nv_bfloat16* __restrict__ vhp,
                     const __nv_bfloat16* __restrict__ vlp,
                     __nv_bfloat16* __restrict__ ath,
                     __nv_bfloat16* __restrict__ atl)
{
    extern __shared__ char smp[];
    const uint32_t sb = smem_to_u32(smp);
    const int tid = threadIdx.x, lane = tid & 31, w = tid >> 5;
    const int qb = 15 - blockIdx.x, h = blockIdx.y, kv = h >> 2;
    const int q0 = qb * 128;

    const uint32_t sQh = sb, sQl = sb + FQ_B;
    const uint32_t sKV = sb + 2 * FQ_B;   // [buf][Khi|Klo|Vhi|Vlo]

    // Q loads (group 0 with KV tile 0)
    {
        const __nv_bfloat16* srch = qhp + (size_t)q0 * HID_ + h * HD_;
        const __nv_bfloat16* srcl = qlp + (size_t)q0 * HID_ + h * HD_;
        #pragma unroll
        for (int c = tid; c < 2048; c += 256) {
            int r = c >> 4, seg = c & 15;
            cp16(sQh + r * FSTR + seg * 16, srch + (size_t)r * HID_ + seg * 8);
            cp16(sQl + r * FSTR + seg * 16, srcl + (size_t)r * HID_ + seg * 8);
        }
    }
    const __nv_bfloat16* kbh = khp + (size_t)kv * S_ * HD_;
    const __nv_bfloat16* kbl = klp + (size_t)kv * S_ * HD_;
    const __nv_bfloat16* vbh = vhp + (size_t)kv * S_ * HD_;
    const __nv_bfloat16* vbl = vlp + (size_t)kv * S_ * HD_;

    auto load_kv = [&](int kt, uint32_t buf) {
        #pragma unroll
        for (int c = tid; c < 1024; c += 256) {
            int r = c >> 4, seg = c & 15;
            size_t g = (size_t)(kt * 64 + r) * HD_ + seg * 8;
            uint32_t so = r * FSTR + seg * 16;
            cp16(buf + so,             kbh + g);
            cp16(buf + FKV_B + so,     kbl + g);
            cp16(buf + 2*FKV_B + so,   vbh + g);
            cp16(buf + 3*FKV_B + so,   vbl + g);
        }
    };
    load_kv(0, sKV);
    CP_COMMIT();

    float o[16][4];
    #pragma unroll
    for (int j = 0; j < 16; ++j)
        #pragma unroll
        for (int q = 0; q < 4; ++q) o[j][q] = 0.f;
    float m0 = -1e30f, m1 = -1e30f, l0 = 0.f, l1 = 0.f;

    const int last = 2 * qb + 1;
    const uint32_t a_off  = (lane & 15) * FSTR + (lane >> 4) * 16;
    const uint32_t bk_off = (lane & 7) * FSTR + ((lane >> 3) & 1) * 16;
    const uint32_t bv_off = (lane & 15) * FSTR;
    const int r0 = q0 + w * 16 + (lane >> 2);   // row for c0,c1 (c2,c3 -> r0+8)

    for (int kt = 0; kt <= last; ++kt) {
        if (kt < last) {
            load_kv(kt + 1, sKV + ((kt + 1) & 1) * 4 * FKV_B);
            CP_COMMIT();
            CP_WAIT(1);
        } else {
            CP_WAIT(0);
        }
        __syncthreads();

        const uint32_t bK = sKV + (kt & 1) * 4 * FKV_B;
        const uint32_t bV = bK + 2 * FKV_B;

        // ---- scores S = Q K^T (hi/lo 3-product) ----
        float s[8][4];
        #pragma unroll
        for (int j = 0; j < 8; ++j)
            #pragma unroll
            for (int q = 0; q < 4; ++q) s[j][q] = 0.f;

        #pragma unroll
        for (int ks = 0; ks < 8; ++ks) {
            uint32_t ah[4], al[4];
            ldm_x4(ah, sQh + w * (16 * FSTR) + a_off + ks * 32);
            ldm_x4(al, sQl + w * (16 * FSTR) + a_off + ks * 32);
            #pragma unroll
            for (int j = 0; j < 8; ++j) {
                uint32_t bh2[2], bl2[2];
                ldm_x2(bh2, bK + j * (8 * FSTR) + bk_off + ks * 32);
                ldm_x2(bl2, bK + FKV_B + j * (8 * FSTR) + bk_off + ks * 32);
                mma_bf16(s[j], ah, bh2);
                mma_bf16(s[j], ah, bl2);
                mma_bf16(s[j], al, bh2);
            }
        }

        // ---- causal mask ----
        if (kt >= 2 * qb) {
            #pragma unroll
            for (int j = 0; j < 8; ++j) {
                int col = kt * 64 + j * 8 + (lane & 3) * 2;
                if (col     > r0)     s[j][0] = -3e4f;
                if (col + 1 > r0)     s[j][1] = -3e4f;
                if (col     > r0 + 8) s[j][2] = -3e4f;
                if (col + 1 > r0 + 8) s[j][3] = -3e4f;
            }
        }

        // ---- row max (quad reduce) ----
        float mx0 = -3e4f, mx1 = -3e4f;
        #pragma unroll
        for (int j = 0; j < 8; ++j) {
            mx0 = fmaxf(mx0, fmaxf(s[j][0], s[j][1]));
            mx1 = fmaxf(mx1, fmaxf(s[j][2], s[j][3]));
        }
        mx0 = fmaxf(mx0, __shfl_xor_sync(0xffffffffu, mx0, 1));
        mx0 = fmaxf(mx0, __shfl_xor_sync(0xffffffffu, mx0, 2));
        mx1 = fmaxf(mx1, __shfl_xor_sync(0xffffffffu, mx1, 1));
        mx1 = fmaxf(mx1, __shfl_xor_sync(0xffffffffu, mx1, 2));

        const float mn0 = fmaxf(m0, mx0), mn1 = fmaxf(m1, mx1);
        const float al0 = fexp2(m0 - mn0), al1 = fexp2(m1 - mn1);
        m0 = mn0; m1 = mn1;

        // ---- exp + row sum ----
        float sum0 = 0.f, sum1 = 0.f;
        #pragma unroll
        for (int j = 0; j < 8; ++j) {
            s[j][0] = fexp2(s[j][0] - mn0);
            s[j][1] = fexp2(s[j][1] - mn0);
            s[j][2] = fexp2(s[j][2] - mn1);
            s[j][3] = fexp2(s[j][3] - mn1);
            sum0 += s[j][0] + s[j][1];
            sum1 += s[j][2] + s[j][3];
        }
        sum0 += __shfl_xor_sync(0xffffffffu, sum0, 1);
        sum0 += __shfl_xor_sync(0xffffffffu, sum0, 2);
        sum1 += __shfl_xor_sync(0xffffffffu, sum1, 1);
        sum1 += __shfl_xor_sync(0xffffffffu, sum1, 2);
        l0 = l0 * al0 + sum0;
        l1 = l1 * al1 + sum1;

        // ---- rescale O ----
        #pragma unroll
        for (int j = 0; j < 16; ++j) {
            o[j][0] *= al0; o[j][1] *= al0;
            o[j][2] *= al1; o[j][3] *= al1;
        }

        // ---- O += P V (hi/lo 3-product) ----
        #pragma unroll
        for (int pk = 0; pk < 4; ++pk) {
            uint32_t phi[4], plo[4];
            pack_hilo(s[2*pk][0],   s[2*pk][1],   phi[0], plo[0]);
            pack_hilo(s[2*pk][2],   s[2*pk][3],   phi[1], plo[1]);
            pack_hilo(s[2*pk+1][0], s[2*pk+1][1], phi[2], plo[2]);
            pack_hilo(s[2*pk+1][2], s[2*pk+1][3], phi[3], plo[3]);
            #pragma unroll
            for (int j = 0; j < 16; ++j) {
                uint32_t bh2[2], bl2[2];
                ldm_x2t(bh2, bV + pk * (16 * FSTR) + bv_off + j * 16);
                ldm_x2t(bl2, bV + FKV_B + pk * (16 * FSTR) + bv_off + j * 16);
                mma_bf16(o[j], phi, bh2);
                mma_bf16(o[j], phi, bl2);
                mma_bf16(o[j], plo, bh2);
            }
        }
        __syncthreads();
    }

    // ---- epilogue: normalize, split to bf16 hi/lo ----
    const float inv0 = 1.f / l0, inv1 = 1.f / l1;
    #pragma unroll
    for (int j = 0; j < 16; ++j) {
        int col = j * 8 + (lane & 3) * 2;
        uint32_t hi, lo;
        pack_hilo(o[j][0] * inv0, o[j][1] * inv0, hi, lo);
        size_t off0 = (size_t)r0 * HID_ + h * HD_ + col;
        *(uint32_t*)&ath[off0] = hi;
        *(uint32_t*)&atl[off0] = lo;
        pack_hilo(o[j][2] * inv1, o[j][3] * inv1, hi, lo);
        size_t off1 = (size_t)(r0 + 8) * HID_ + h * HD_ + col;
        *(uint32_t*)&ath[off1] = hi;
        *(uint32_t*)&atl[off1] = lo;
    }
}

// ---------------------------------------------------------------------------
extern "C" void kernel_launch(void* const* d_in, const int* in_sizes, int n_in,
                              void* d_out, int out_size)
{
    const float* hs  = (const float*)d_in[0];
    const int*   pos = (const int*)  d_in[1];
    const float* Wq  = (const float*)d_in[3];
    const float* Wk  = (const float*)d_in[4];
    const float* Wv  = (const float*)d_in[5];
    const float* Wo  = (const float*)d_in[6];

    float* out  = (float*)d_out;                       // [S, HID]
    float* kout = out  + (size_t)S_ * HID_;            // [NH, S, HD] (repeated)
    float* vout = kout + (size_t)NH_ * S_ * HD_;       // [NH, S, HD] (repeated)

    float *qp, *kp, *vp;
    cudaGetSymbolAddress((void**)&qp, g_q);
    cudaGetSymbolAddress((void**)&kp, g_k);
    cudaGetSymbolAddress((void**)&vp, g_v);
    __nv_bfloat16 *hsh, *hsl, *wqh, *wql, *wkh, *wkl, *wvh, *wvl, *woh, *wol, *ath, *atl;
    __nv_bfloat16 *qbh, *qbl, *kbh, *kbl, *vbh, *vbl;
    cudaGetSymbolAddress((void**)&hsh, g_hs_hi); cudaGetSymbolAddress((void**)&hsl, g_hs_lo);
    cudaGetSymbolAddress((void**)&wqh, g_wq_hi); cudaGetSymbolAddress((void**)&wql, g_wq_lo);
    cudaGetSymbolAddress((void**)&wkh, g_wk_hi); cudaGetSymbolAddress((void**)&wkl, g_wk_lo);
    cudaGetSymbolAddress((void**)&wvh, g_wv_hi); cudaGetSymbolAddress((void**)&wvl, g_wv_lo);
    cudaGetSymbolAddress((void**)&woh, g_wo_hi); cudaGetSymbolAddress((void**)&wol, g_wo_lo);
    cudaGetSymbolAddress((void**)&ath, g_at_hi); cudaGetSymbolAddress((void**)&atl, g_at_lo);
    cudaGetSymbolAddress((void**)&qbh, g_qb_hi); cudaGetSymbolAddress((void**)&qbl, g_qb_lo);
    cudaGetSymbolAddress((void**)&kbh, g_kb_hi); cudaGetSymbolAddress((void**)&kbl, g_kb_lo);
    cudaGetSymbolAddress((void**)&vbh, g_vb_hi); cudaGetSymbolAddress((void**)&vbl, g_vb_lo);

    cudaFuncSetAttribute(qkv_gemm_kernel,
                         cudaFuncAttributeMaxDynamicSharedMemorySize, GEMM_SMEM);
    cudaFuncSetAttribute(gemm_mma_kernel,
                         cudaFuncAttributeMaxDynamicSharedMemorySize, GEMM_SMEM);
    cudaFuncSetAttribute(flash_tc_kernel,
                         cudaFuncAttributeMaxDynamicSharedMemorySize, FLASH_SMEM);

    // input conversions
    conv_split_kernel<<<(S_*HID_/4)/256, 256>>>(hs, hsh, hsl);
    transpose_split_kernel<<<dim3(HID_/32, HID_/32), dim3(32,8)>>>(Wq, wqh, wql, HID_, HID_);
    transpose_split_kernel<<<dim3(KVD_/32, HID_/32), dim3(32,8)>>>(Wk, wkh, wkl, HID_, KVD_);
    transpose_split_kernel<<<dim3(KVD_/32, HID_/32), dim3(32,8)>>>(Wv, wvh, wvl, HID_, KVD_);
    transpose_split_kernel<<<dim3(HID_/32, HID_/32), dim3(32,8)>>>(Wo, woh, wol, HID_, HID_);

    // fused QKV projection (tensor core, bf16x3)
    qkv_gemm_kernel<<<dim3(24, S_/128), 256, GEMM_SMEM>>>(
        hsh, hsl, wqh, wql, wkh, wkl, wvh, wvl, qp, kp, vp);

    // rope + layout (+ compact bf16 copies for flash)
    rope_q_kernel<<<(NH_*S_*64)/256, 256>>>(pos, qbh, qbl);
    rope_k_kernel<<<(NKV_*S_*64)/256, 256>>>(pos, kout, kbh, kbl);
    copy_v_kernel<<<(NKV_*S_*32)/256, 256>>>(vout, vbh, vbl);

    // attention (tensor core flash) -> bf16 hi/lo
    flash_tc_kernel<<<dim3(16, NH_), 256, FLASH_SMEM>>>(
        qbh, qbl, kbh, kbl, vbh, vbl, ath, atl);

    // output projection (tensor core, bf16x3)
    gemm_mma_kernel<<<dim3(HID_/128, S_/128), 256, GEMM_SMEM>>>(
        ath, atl, woh, wol, out, HID_, HID_);
}

// round 6
// speedup vs baseline: 5.1257x; 1.2645x over previous
#include <cuda_runtime.h>
#include <cuda_fp16.h>
#include <math.h>
#include <stdint.h>

#define S_   2048
#define HID_ 2048
#define NH_  16
#define NKV_ 4
#define GRP_ (NH_/NKV_)   // 4
#define HD_  128
#define KVD_ (NKV_*HD_)   // 512

// scale * log2(e), folded into Q at rope time
#define SCL_LOG2E 0.12751744f

// ---------------------------------------------------------------------------
// scratch (allocation-free: __device__ globals)
// ---------------------------------------------------------------------------
__device__ float g_q  [S_*HID_];   // Q projection (fp32)
__device__ float g_k  [S_*KVD_];   // K projection pre-rope
__device__ float g_v  [S_*KVD_];   // V projection

__device__ __half g_hs_hi[S_*HID_],  g_hs_lo[S_*HID_];    // hidden [m][k] (A split)
__device__ __half g_wq[HID_*HID_];                        // weights [n][k] single fp16
__device__ __half g_wk[KVD_*HID_];
__device__ __half g_wv[KVD_*HID_];
__device__ __half g_wo[HID_*HID_];
__device__ __half g_at_hi[S_*HID_],  g_at_lo[S_*HID_];    // attn out [m][k] (A split)

__device__ __half g_qb_hi[S_*HID_],  g_qb_lo[S_*HID_];    // roped Q*scl (A split)
__device__ __half g_kb[NKV_*S_*HD_];                      // K single [kv][s][d]
__device__ __half g_vb_hi[NKV_*S_*HD_], g_vb_lo[NKV_*S_*HD_]; // V split

// ---------------------------------------------------------------------------
// PTX helpers (plain sm_103-safe)
// ---------------------------------------------------------------------------
__device__ __forceinline__ uint32_t smem_to_u32(const void* p) {
    uint32_t a;
    asm("{ .reg .u64 t; cvta.to.shared.u64 t, %1; cvt.u32.u64 %0, t; }"
        : "=r"(a) : "l"(p));
    return a;
}
__device__ __forceinline__ void cp16(uint32_t dst, const void* src) {
    asm volatile("cp.async.cg.shared.global [%0], [%1], 16;" :: "r"(dst), "l"(src));
}
#define CP_COMMIT() asm volatile("cp.async.commit_group;" ::: "memory")
#define CP_WAIT(n)  asm volatile("cp.async.wait_group %0;" :: "n"(n) : "memory")

__device__ __forceinline__ void ldm_x4(uint32_t* r, uint32_t addr) {
    asm volatile("ldmatrix.sync.aligned.m8n8.x4.shared.b16 {%0,%1,%2,%3}, [%4];"
        : "=r"(r[0]), "=r"(r[1]), "=r"(r[2]), "=r"(r[3]) : "r"(addr));
}
__device__ __forceinline__ void ldm_x2(uint32_t* r, uint32_t addr) {
    asm volatile("ldmatrix.sync.aligned.m8n8.x2.shared.b16 {%0,%1}, [%2];"
        : "=r"(r[0]), "=r"(r[1]) : "r"(addr));
}
__device__ __forceinline__ void ldm_x2t(uint32_t* r, uint32_t addr) {
    asm volatile("ldmatrix.sync.aligned.m8n8.x2.trans.shared.b16 {%0,%1}, [%2];"
        : "=r"(r[0]), "=r"(r[1]) : "r"(addr));
}
__device__ __forceinline__ void mma_f16(float* c, const uint32_t* a, const uint32_t* b) {
    asm volatile("mma.sync.aligned.m16n8k16.row.col.f32.f16.f16.f32 "
        "{%0,%1,%2,%3}, {%4,%5,%6,%7}, {%8,%9}, {%0,%1,%2,%3};"
        : "+f"(c[0]), "+f"(c[1]), "+f"(c[2]), "+f"(c[3])
        : "r"(a[0]), "r"(a[1]), "r"(a[2]), "r"(a[3]), "r"(b[0]), "r"(b[1]));
}

// pack x (low half) and y (high half) into f16x2, plus residual pack
__device__ __forceinline__ void pack_hilo(float x, float y, uint32_t& hi, uint32_t& lo) {
    __half hx = __float2half_rn(x), hy = __float2half_rn(y);
    float rx = x - __half2float(hx), ry = y - __half2float(hy);
    __half lx = __float2half_rn(rx), ly = __float2half_rn(ry);
    union { __half2 h2; uint32_t u; } H, L;
    H.h2 = __halves2half2(hx, hy);
    L.h2 = __halves2half2(lx, ly);
    hi = H.u; lo = L.u;
}

// fast 2^x on FMA pipe (x <= ~0, clamped)
__device__ __forceinline__ float fexp2(float x) {
    x = fmaxf(x, -126.0f);
    int e = __float2int_rn(x);
    float f = x - (float)e;
    float p = 0.0018775767f;
    p = fmaf(p, f, 0.0089893397f);
    p = fmaf(p, f, 0.0558040221f);
    p = fmaf(p, f, 0.2402264923f);
    p = fmaf(p, f, 0.6931471825f);
    p = fmaf(p, f, 1.0f);
    return __int_as_float(__float_as_int(p) + (e << 23));
}

__device__ __forceinline__ void split_f16(float v, __half* hi, __half* lo) {
    __half h = __float2half_rn(v);
    *hi = h;
    *lo = __float2half_rn(v - __half2float(h));
}

// ---------------------------------------------------------------------------
// fp32 -> fp16 hi/lo split (no transpose)
// ---------------------------------------------------------------------------
__global__ void conv_split_kernel(const float* __restrict__ src,
                                  __half* __restrict__ hi,
                                  __half* __restrict__ lo)
{
    int i = blockIdx.x * 256 + threadIdx.x;
    float4 v = ((const float4*)src)[i];
    float f[4] = {v.x, v.y, v.z, v.w};
    union { uint2 u; __half b[4]; } H, L;
    #pragma unroll
    for (int j = 0; j < 4; ++j) split_f16(f[j], &H.b[j], &L.b[j]);
    ((uint2*)hi)[i] = H.u;
    ((uint2*)lo)[i] = L.u;
}

// fp32 W[Kd][Nd] -> single fp16 [Nd][Kd] (transpose)
__global__ void transpose_half_kernel(const float* __restrict__ W,
                                      __half* __restrict__ out,
                                      int Kd, int Nd)
{
    __shared__ float t[32][33];
    int bn = blockIdx.x * 32;
    int bk = blockIdx.y * 32;
    int x = threadIdx.x, y = threadIdx.y;   // (32, 8)
    #pragma unroll
    for (int i = 0; i < 32; i += 8)
        t[y + i][x] = W[(size_t)(bk + y + i) * Nd + bn + x];
    __syncthreads();
    #pragma unroll
    for (int i = 0; i < 32; i += 8)
        out[(size_t)(bn + y + i) * Kd + bk + x] = __float2half_rn(t[x][y + i]);
}

// ---------------------------------------------------------------------------
// mma.sync GEMM: C = (Ah+Al) @ Bh^T, 2 products. 128x128 tile, K-chunks of 32.
// smem tiles: 128 x 32 fp16, row stride 80 B. Buffer: [Ah|Al|Bh].
// ---------------------------------------------------------------------------
#define TILE_B   10240              // 128*80
#define BUF_B    (3*TILE_B)         // 30720
#define GEMM_SMEM (2*BUF_B)         // 61440

__device__ __forceinline__ void load_tile_async(uint32_t sdst,
                                                const __half* g,
                                                int ldk, int tid)
{
    int r   = tid >> 2;
    int seg = tid & 3;
    #pragma unroll
    for (int h = 0; h < 2; ++h) {
        int row = r + h * 64;
        cp16(sdst + row * 80 + seg * 16, g + (size_t)row * ldk + seg * 8);
    }
}

__device__ __forceinline__ void gemm_body(
    uint32_t sb,
    const __half* Ahi, const __half* Alo, const __half* Bh,
    float* C, int N, int K, int tid)
{
    const int lane = tid & 31, wid = tid >> 5;
    const int wm = wid & 1, wn = wid >> 1;

    float acc[4][4][4];
    #pragma unroll
    for (int mi = 0; mi < 4; ++mi)
        #pragma unroll
        for (int ni = 0; ni < 4; ++ni)
            #pragma unroll
            for (int q = 0; q < 4; ++q) acc[mi][ni][q] = 0.f;

    const int T = K / 32;
    load_tile_async(sb,            Ahi, K, tid);
    load_tile_async(sb +   TILE_B, Alo, K, tid);
    load_tile_async(sb + 2*TILE_B, Bh,  K, tid);
    CP_COMMIT();

    const uint32_t a_lane_off = (uint32_t)((lane & 15) * 80 + (lane >> 4) * 16);
    const uint32_t b_lane_off = (uint32_t)((lane & 7) * 80 + ((lane >> 3) & 1) * 16);

    for (int kt = 0; kt < T; ++kt) {
        if (kt + 1 < T) {
            uint32_t nb = sb + ((kt + 1) & 1) * BUF_B;
            int k0 = (kt + 1) * 32;
            load_tile_async(nb,            Ahi + k0, K, tid);
            load_tile_async(nb +   TILE_B, Alo + k0, K, tid);
            load_tile_async(nb + 2*TILE_B, Bh  + k0, K, tid);
            CP_COMMIT();
            CP_WAIT(1);
        } else {
            CP_WAIT(0);
        }
        __syncthreads();

        uint32_t buf = sb + (kt & 1) * BUF_B;
        #pragma unroll
        for (int ks = 0; ks < 2; ++ks) {
            uint32_t ah[4][4], al[4][4], bh[4][2];
            uint32_t abase = buf + wm * (64 * 80) + a_lane_off + ks * 32;
            #pragma unroll
            for (int mi = 0; mi < 4; ++mi) {
                ldm_x4(ah[mi], abase + mi * (16 * 80));
                ldm_x4(al[mi], abase + TILE_B + mi * (16 * 80));
            }
            uint32_t bbase = buf + 2*TILE_B + wn * (32 * 80) + b_lane_off + ks * 32;
            #pragma unroll
            for (int ni = 0; ni < 4; ++ni)
                ldm_x2(bh[ni], bbase + ni * (8 * 80));
            #pragma unroll
            for (int mi = 0; mi < 4; ++mi)
                #pragma unroll
                for (int ni = 0; ni < 4; ++ni) {
                    mma_f16(acc[mi][ni], ah[mi], bh[ni]);
                    mma_f16(acc[mi][ni], al[mi], bh[ni]);
                }
        }
        __syncthreads();
    }

    #pragma unroll
    for (int mi = 0; mi < 4; ++mi) {
        int row = wm * 64 + mi * 16 + (lane >> 2);
        #pragma unroll
        for (int ni = 0; ni < 4; ++ni) {
            int col = wn * 32 + ni * 8 + (lane & 3) * 2;
            *(float2*)&C[(size_t)row * N + col] =
                make_float2(acc[mi][ni][0], acc[mi][ni][1]);
            *(float2*)&C[(size_t)(row + 8) * N + col] =
                make_float2(acc[mi][ni][2], acc[mi][ni][3]);
        }
    }
}

__global__ __launch_bounds__(256, 1)
void qkv_gemm_kernel(const __half* __restrict__ Ahi,
                     const __half* __restrict__ Alo,
                     const __half* __restrict__ Wq,
                     const __half* __restrict__ Wk,
                     const __half* __restrict__ Wv,
                     float* __restrict__ Cq, float* __restrict__ Ck,
                     float* __restrict__ Cv)
{
    extern __shared__ char smp[];
    uint32_t sb = smem_to_u32(smp);
    const int nb = blockIdx.x;
    const int bm = blockIdx.y * 128;
    const __half* Bh;
    float* C;
    int N, bn;
    if (nb < 16)      { Bh = Wq; C = Cq; N = HID_; bn = nb * 128; }
    else if (nb < 20) { Bh = Wk; C = Ck; N = KVD_; bn = (nb - 16) * 128; }
    else              { Bh = Wv; C = Cv; N = KVD_; bn = (nb - 20) * 128; }
    gemm_body(sb,
              Ahi + (size_t)bm * HID_, Alo + (size_t)bm * HID_,
              Bh + (size_t)bn * HID_,
              C + (size_t)bm * N + bn, N, HID_, threadIdx.x);
}

__global__ __launch_bounds__(256, 1)
void gemm_mma_kernel(const __half* __restrict__ Ahi,
                     const __half* __restrict__ Alo,
                     const __half* __restrict__ Bh,
                     float* __restrict__ C, int N, int K)
{
    extern __shared__ char smp[];
    uint32_t sb = smem_to_u32(smp);
    const int bm = blockIdx.y * 128, bn = blockIdx.x * 128;
    gemm_body(sb,
              Ahi + (size_t)bm * K, Alo + (size_t)bm * K,
              Bh + (size_t)bn * K,
              C + (size_t)bm * N + bn, N, K, threadIdx.x);
}

// ---------------------------------------------------------------------------
// RoPE (pure fp32)
// ---------------------------------------------------------------------------
__device__ __forceinline__ void rope_pair(float x1, float x2, int pos, int d,
                                          float& o1, float& o2)
{
    float inv = exp2f((float)d * (-13.287712379549449f / 64.0f));
    float ang = (float)pos * inv;
    float sn, cs;
    sincosf(ang, &sn, &cs);
    o1 = x1 * cs - x2 * sn;
    o2 = x1 * sn + x2 * cs;
}

// Q: rope + scale(SCL_LOG2E), write fp16 hi/lo
__global__ void rope_q_kernel(const int* __restrict__ positions,
                              __half* __restrict__ qh,
                              __half* __restrict__ ql)
{
    int idx = blockIdx.x * blockDim.x + threadIdx.x;   // NH*S*64
    int d = idx & 63;
    int s = (idx >> 6) & (S_ - 1);
    int h = idx >> 17;
    size_t base = (size_t)s * HID_ + h * HD_;
    float x1 = g_q[base + d], x2 = g_q[base + d + 64];
    float o1, o2;
    rope_pair(x1, x2, positions[s], d, o1, o2);
    o1 *= SCL_LOG2E; o2 *= SCL_LOG2E;
    split_f16(o1, &qh[base + d],      &ql[base + d]);
    split_f16(o2, &qh[base + d + 64], &ql[base + d + 64]);
}

// K: rope; fp32 repeated -> kout[h][s][d]; fp16 single compact [kv][s][d]
__global__ void rope_k_kernel(const int* __restrict__ positions,
                              float* __restrict__ kout,
                              __half* __restrict__ kb)
{
    int idx = blockIdx.x * blockDim.x + threadIdx.x;   // NKV*S*64
    int d  = idx & 63;
    int s  = (idx >> 6) & (S_ - 1);
    int kv = idx >> 17;
    size_t src = (size_t)s * KVD_ + kv * HD_;
    float x1 = g_k[src + d], x2 = g_k[src + d + 64];
    float o1, o2;
    rope_pair(x1, x2, positions[s], d, o1, o2);
    #pragma unroll
    for (int g = 0; g < GRP_; ++g) {
        size_t dst = ((size_t)(kv * GRP_ + g) * S_ + s) * HD_;
        kout[dst + d] = o1; kout[dst + d + 64] = o2;
    }
    size_t cb = ((size_t)kv * S_ + s) * HD_;
    kb[cb + d]      = __float2half_rn(o1);
    kb[cb + d + 64] = __float2half_rn(o2);
}

// V: fp32 repeated -> vout; fp16 hi/lo compact
__global__ void copy_v_kernel(float* __restrict__ vout,
                              __half* __restrict__ vbh,
                              __half* __restrict__ vbl)
{
    int idx = blockIdx.x * blockDim.x + threadIdx.x;   // NKV*S*32 float4s
    int d4 = idx & 31;
    int s  = (idx >> 5) & (S_ - 1);
    int kv = idx >> 16;
    float4 v = *(const float4*)&g_v[(size_t)s * KVD_ + kv * HD_ + d4 * 4];
    #pragma unroll
    for (int g = 0; g < GRP_; ++g)
        *(float4*)&vout[((size_t)(kv * GRP_ + g) * S_ + s) * HD_ + d4 * 4] = v;
    size_t cb = ((size_t)kv * S_ + s) * HD_ + d4 * 4;
    float f[4] = {v.x, v.y, v.z, v.w};
    union { uint2 u; __half b[4]; } H, L;
    #pragma unroll
    for (int j = 0; j < 4; ++j) split_f16(f[j], &H.b[j], &L.b[j]);
    *(uint2*)&vbh[cb] = H.u;
    *(uint2*)&vbl[cb] = L.u;
}

// ---------------------------------------------------------------------------
// Tensor-core flash attention: BQ=128, BK=64, HD=128, 8 warps.
// QK: (Qh+Ql)*Kh (2 products). PV: Ph*Vh + Ph*Vl + Pl*Vh (3 products).
// ---------------------------------------------------------------------------
#define FSTR  272                   // bytes per smem row (256 + 16 pad)
#define FQ_B  (128*FSTR)            // 34816
#define FKV_B (64*FSTR)             // 17408
#define FLASH_SMEM (2*FQ_B + 6*FKV_B)  // 174080

__global__ __launch_bounds__(256, 1)
void flash_tc_kernel(const __half* __restrict__ qhp,
                     const __half* __restrict__ qlp,
                     const __half* __restrict__ khp,
                     const __half* __restrict__ vhp,
                     const __half* __restrict__ vlp,
                     __half* __restrict__ ath,
                     __half* __restrict__ atl)
{
    extern __shared__ char smp[];
    const uint32_t sb = smem_to_u32(smp);
    const int tid = threadIdx.x, lane = tid & 31, w = tid >> 5;
    const int qb = 15 - blockIdx.x, h = blockIdx.y, kv = h >> 2;
    const int q0 = qb * 128;

    const uint32_t sQh = sb, sQl = sb + FQ_B;
    const uint32_t sKV = sb + 2 * FQ_B;   // per buffer: [Kh | Vh | Vl]

    {
        const __half* srch = qhp + (size_t)q0 * HID_ + h * HD_;
        const __half* srcl = qlp + (size_t)q0 * HID_ + h * HD_;
        #pragma unroll
        for (int c = tid; c < 2048; c += 256) {
            int r = c >> 4, seg = c & 15;
            cp16(sQh + r * FSTR + seg * 16, srch + (size_t)r * HID_ + seg * 8);
            cp16(sQl + r * FSTR + seg * 16, srcl + (size_t)r * HID_ + seg * 8);
        }
    }
    const __half* kb  = khp + (size_t)kv * S_ * HD_;
    const __half* vbh = vhp + (size_t)kv * S_ * HD_;
    const __half* vbl = vlp + (size_t)kv * S_ * HD_;

    auto load_kv = [&](int kt, uint32_t buf) {
        #pragma unroll
        for (int c = tid; c < 1024; c += 256) {
            int r = c >> 4, seg = c & 15;
            size_t g = (size_t)(kt * 64 + r) * HD_ + seg * 8;
            uint32_t so = r * FSTR + seg * 16;
            cp16(buf + so,             kb  + g);
            cp16(buf + FKV_B + so,     vbh + g);
            cp16(buf + 2*FKV_B + so,   vbl + g);
        }
    };
    load_kv(0, sKV);
    CP_COMMIT();

    float o[16][4];
    #pragma unroll
    for (int j = 0; j < 16; ++j)
        #pragma unroll
        for (int q = 0; q < 4; ++q) o[j][q] = 0.f;
    float m0 = -1e30f, m1 = -1e30f, l0 = 0.f, l1 = 0.f;

    const int last = 2 * qb + 1;
    const uint32_t a_off  = (lane & 15) * FSTR + (lane >> 4) * 16;
    const uint32_t bk_off = (lane & 7) * FSTR + ((lane >> 3) & 1) * 16;
    const uint32_t bv_off = (lane & 15) * FSTR;
    const int r0 = q0 + w * 16 + (lane >> 2);

    for (int kt = 0; kt <= last; ++kt) {
        if (kt < last) {
            load_kv(kt + 1, sKV + ((kt + 1) & 1) * 3 * FKV_B);
            CP_COMMIT();
            CP_WAIT(1);
        } else {
            CP_WAIT(0);
        }
        __syncthreads();

        const uint32_t bK = sKV + (kt & 1) * 3 * FKV_B;
        const uint32_t bV = bK + FKV_B;

        // ---- scores S = (Qh+Ql) Kh^T ----
        float s[8][4];
        #pragma unroll
        for (int j = 0; j < 8; ++j)
            #pragma unroll
            for (int q = 0; q < 4; ++q) s[j][q] = 0.f;

        #pragma unroll
        for (int ks = 0; ks < 8; ++ks) {
            uint32_t ah[4], al[4];
            ldm_x4(ah, sQh + w * (16 * FSTR) + a_off + ks * 32);
            ldm_x4(al, sQl + w * (16 * FSTR) + a_off + ks * 32);
            #pragma unroll
            for (int j = 0; j < 8; ++j) {
                uint32_t bh2[2];
                ldm_x2(bh2, bK + j * (8 * FSTR) + bk_off + ks * 32);
                mma_f16(s[j], ah, bh2);
                mma_f16(s[j], al, bh2);
            }
        }

        // ---- causal mask ----
        if (kt >= 2 * qb) {
            #pragma unroll
            for (int j = 0; j < 8; ++j) {
                int col = kt * 64 + j * 8 + (lane & 3) * 2;
                if (col     > r0)     s[j][0] = -3e4f;
                if (col + 1 > r0)     s[j][1] = -3e4f;
                if (col     > r0 + 8) s[j][2] = -3e4f;
                if (col + 1 > r0 + 8) s[j][3] = -3e4f;
            }
        }

        // ---- row max (quad reduce) ----
        float mx0 = -3e4f, mx1 = -3e4f;
        #pragma unroll
        for (int j = 0; j < 8; ++j) {
            mx0 = fmaxf(mx0, fmaxf(s[j][0], s[j][1]));
            mx1 = fmaxf(mx1, fmaxf(s[j][2], s[j][3]));
        }
        mx0 = fmaxf(mx0, __shfl_xor_sync(0xffffffffu, mx0, 1));
        mx0 = fmaxf(mx0, __shfl_xor_sync(0xffffffffu, mx0, 2));
        mx1 = fmaxf(mx1, __shfl_xor_sync(0xffffffffu, mx1, 1));
        mx1 = fmaxf(mx1, __shfl_xor_sync(0xffffffffu, mx1, 2));

        const float mn0 = fmaxf(m0, mx0), mn1 = fmaxf(m1, mx1);
        const float al0 = fexp2(m0 - mn0), al1 = fexp2(m1 - mn1);
        m0 = mn0; m1 = mn1;

        // ---- exp + row sum ----
        float sum0 = 0.f, sum1 = 0.f;
        #pragma unroll
        for (int j = 0; j < 8; ++j) {
            s[j][0] = fexp2(s[j][0] - mn0);
            s[j][1] = fexp2(s[j][1] - mn0);
            s[j][2] = fexp2(s[j][2] - mn1);
            s[j][3] = fexp2(s[j][3] - mn1);
            sum0 += s[j][0] + s[j][1];
            sum1 += s[j][2] + s[j][3];
        }
        sum0 += __shfl_xor_sync(0xffffffffu, sum0, 1);
        sum0 += __shfl_xor_sync(0xffffffffu, sum0, 2);
        sum1 += __shfl_xor_sync(0xffffffffu, sum1, 1);
        sum1 += __shfl_xor_sync(0xffffffffu, sum1, 2);
        l0 = l0 * al0 + sum0;
        l1 = l1 * al1 + sum1;

        // ---- rescale O ----
        #pragma unroll
        for (int j = 0; j < 16; ++j) {
            o[j][0] *= al0; o[j][1] *= al0;
            o[j][2] *= al1; o[j][3] *= al1;
        }

        // ---- O += P V (P hi/lo, V hi/lo, 3 products) ----
        #pragma unroll
        for (int pk = 0; pk < 4; ++pk) {
            uint32_t phi[4], plo[4];
            pack_hilo(s[2*pk][0],   s[2*pk][1],   phi[0], plo[0]);
            pack_hilo(s[2*pk][2],   s[2*pk][3],   phi[1], plo[1]);
            pack_hilo(s[2*pk+1][0], s[2*pk+1][1], phi[2], plo[2]);
            pack_hilo(s[2*pk+1][2], s[2*pk+1][3], phi[3], plo[3]);
            #pragma unroll
            for (int j = 0; j < 16; ++j) {
                uint32_t bh2[2], bl2[2];
                ldm_x2t(bh2, bV + pk * (16 * FSTR) + bv_off + j * 16);
                ldm_x2t(bl2, bV + FKV_B + pk * (16 * FSTR) + bv_off + j * 16);
                mma_f16(o[j], phi, bh2);
                mma_f16(o[j], phi, bl2);
                mma_f16(o[j], plo, bh2);
            }
        }
        __syncthreads();
    }

    // ---- epilogue: normalize, split to fp16 hi/lo ----
    const float inv0 = 1.f / l0, inv1 = 1.f / l1;
    #pragma unroll
    for (int j = 0; j < 16; ++j) {
        int col = j * 8 + (lane & 3) * 2;
        uint32_t hi, lo;
        pack_hilo(o[j][0] * inv0, o[j][1] * inv0, hi, lo);
        size_t off0 = (size_t)r0 * HID_ + h * HD_ + col;
        *(uint32_t*)&ath[off0] = hi;
        *(uint32_t*)&atl[off0] = lo;
        pack_hilo(o[j][2] * inv1, o[j][3] * inv1, hi, lo);
        size_t off1 = (size_t)(r0 + 8) * HID_ + h * HD_ + col;
        *(uint32_t*)&ath[off1] = hi;
        *(uint32_t*)&atl[off1] = lo;
    }
}

// ---------------------------------------------------------------------------
extern "C" void kernel_launch(void* const* d_in, const int* in_sizes, int n_in,
                              void* d_out, int out_size)
{
    const float* hs  = (const float*)d_in[0];
    const int*   pos = (const int*)  d_in[1];
    const float* Wq  = (const float*)d_in[3];
    const float* Wk  = (const float*)d_in[4];
    const float* Wv  = (const float*)d_in[5];
    const float* Wo  = (const float*)d_in[6];

    float* out  = (float*)d_out;                       // [S, HID]
    float* kout = out  + (size_t)S_ * HID_;            // [NH, S, HD] (repeated)
    float* vout = kout + (size_t)NH_ * S_ * HD_;       // [NH, S, HD] (repeated)

    float *qp, *kp, *vp;
    cudaGetSymbolAddress((void**)&qp, g_q);
    cudaGetSymbolAddress((void**)&kp, g_k);
    cudaGetSymbolAddress((void**)&vp, g_v);
    __half *hsh, *hsl, *wq, *wk, *wv, *wo, *ath, *atl;
    __half *qbh, *qbl, *kb, *vbh, *vbl;
    cudaGetSymbolAddress((void**)&hsh, g_hs_hi); cudaGetSymbolAddress((void**)&hsl, g_hs_lo);
    cudaGetSymbolAddress((void**)&wq, g_wq);
    cudaGetSymbolAddress((void**)&wk, g_wk);
    cudaGetSymbolAddress((void**)&wv, g_wv);
    cudaGetSymbolAddress((void**)&wo, g_wo);
    cudaGetSymbolAddress((void**)&ath, g_at_hi); cudaGetSymbolAddress((void**)&atl, g_at_lo);
    cudaGetSymbolAddress((void**)&qbh, g_qb_hi); cudaGetSymbolAddress((void**)&qbl, g_qb_lo);
    cudaGetSymbolAddress((void**)&kb, g_kb);
    cudaGetSymbolAddress((void**)&vbh, g_vb_hi); cudaGetSymbolAddress((void**)&vbl, g_vb_lo);

    cudaFuncSetAttribute(qkv_gemm_kernel,
                         cudaFuncAttributeMaxDynamicSharedMemorySize, GEMM_SMEM);
    cudaFuncSetAttribute(gemm_mma_kernel,
                         cudaFuncAttributeMaxDynamicSharedMemorySize, GEMM_SMEM);
    cudaFuncSetAttribute(flash_tc_kernel,
                         cudaFuncAttributeMaxDynamicSharedMemorySize, FLASH_SMEM);

    // input conversions
    conv_split_kernel<<<(S_*HID_/4)/256, 256>>>(hs, hsh, hsl);
    transpose_half_kernel<<<dim3(HID_/32, HID_/32), dim3(32,8)>>>(Wq, wq, HID_, HID_);
    transpose_half_kernel<<<dim3(KVD_/32, HID_/32), dim3(32,8)>>>(Wk, wk, HID_, KVD_);
    transpose_half_kernel<<<dim3(KVD_/32, HID_/32), dim3(32,8)>>>(Wv, wv, HID_, KVD_);
    transpose_half_kernel<<<dim3(HID_/32, HID_/32), dim3(32,8)>>>(Wo, wo, HID_, HID_);

    // fused QKV projection (2-product fp16)
    qkv_gemm_kernel<<<dim3(24, S_/128), 256, GEMM_SMEM>>>(
        hsh, hsl, wq, wk, wv, qp, kp, vp);

    // rope + layout (+ compact fp16 copies for flash)
    rope_q_kernel<<<(NH_*S_*64)/256, 256>>>(pos, qbh, qbl);
    rope_k_kernel<<<(NKV_*S_*64)/256, 256>>>(pos, kout, kb);
    copy_v_kernel<<<(NKV_*S_*32)/256, 256>>>(vout, vbh, vbl);

    // attention (tensor core flash) -> fp16 hi/lo
    flash_tc_kernel<<<dim3(16, NH_), 256, FLASH_SMEM>>>(
        qbh, qbl, kb, vbh, vbl, ath, atl);

    // output projection (2-product fp16)
    gemm_mma_kernel<<<dim3(HID_/128, S_/128), 256, GEMM_SMEM>>>(
        ath, atl, wo, out, HID_, HID_);
}

// round 7
// speedup vs baseline: 5.4812x; 1.0694x over previous
#include <cuda_runtime.h>
#include <cuda_fp16.h>
#include <math.h>
#include <stdint.h>

#define S_   2048
#define HID_ 2048
#define NH_  16
#define NKV_ 4
#define GRP_ (NH_/NKV_)   // 4
#define HD_  128
#define KVD_ (NKV_*HD_)   // 512

// scale * log2(e), folded into Q at rope time
#define SCL_LOG2E 0.12751744f

// ---------------------------------------------------------------------------
// scratch (allocation-free: __device__ globals)
// ---------------------------------------------------------------------------
__device__ float g_q  [S_*HID_];   // Q projection (fp32)
__device__ float g_k  [S_*KVD_];   // K projection pre-rope
__device__ float g_v  [S_*KVD_];   // V projection

__device__ __half g_hs_hi[S_*HID_],  g_hs_lo[S_*HID_];    // hidden [m][k] (A split)
__device__ __half g_wq[HID_*HID_];                        // weights [n][k] single fp16
__device__ __half g_wk[KVD_*HID_];
__device__ __half g_wv[KVD_*HID_];
__device__ __half g_wo[HID_*HID_];
__device__ __half g_at_hi[S_*HID_],  g_at_lo[S_*HID_];    // attn out [m][k] (A split)

__device__ __half g_qb_hi[S_*HID_],  g_qb_lo[S_*HID_];    // roped Q*scl (A split)
__device__ __half g_kb[NKV_*S_*HD_];                      // K single [kv][s][d]
__device__ __half g_vb[NKV_*S_*HD_];                      // V single [kv][s][d]

// ---------------------------------------------------------------------------
// PTX helpers (plain sm_103-safe)
// ---------------------------------------------------------------------------
__device__ __forceinline__ uint32_t smem_to_u32(const void* p) {
    uint32_t a;
    asm("{ .reg .u64 t; cvta.to.shared.u64 t, %1; cvt.u32.u64 %0, t; }"
        : "=r"(a) : "l"(p));
    return a;
}
__device__ __forceinline__ void cp16(uint32_t dst, const void* src) {
    asm volatile("cp.async.cg.shared.global [%0], [%1], 16;" :: "r"(dst), "l"(src));
}
#define CP_COMMIT() asm volatile("cp.async.commit_group;" ::: "memory")
#define CP_WAIT(n)  asm volatile("cp.async.wait_group %0;" :: "n"(n) : "memory")

__device__ __forceinline__ void ldm_x4(uint32_t* r, uint32_t addr) {
    asm volatile("ldmatrix.sync.aligned.m8n8.x4.shared.b16 {%0,%1,%2,%3}, [%4];"
        : "=r"(r[0]), "=r"(r[1]), "=r"(r[2]), "=r"(r[3]) : "r"(addr));
}
__device__ __forceinline__ void ldm_x2(uint32_t* r, uint32_t addr) {
    asm volatile("ldmatrix.sync.aligned.m8n8.x2.shared.b16 {%0,%1}, [%2];"
        : "=r"(r[0]), "=r"(r[1]) : "r"(addr));
}
__device__ __forceinline__ void ldm_x2t(uint32_t* r, uint32_t addr) {
    asm volatile("ldmatrix.sync.aligned.m8n8.x2.trans.shared.b16 {%0,%1}, [%2];"
        : "=r"(r[0]), "=r"(r[1]) : "r"(addr));
}
__device__ __forceinline__ void mma_f16(float* c, const uint32_t* a, const uint32_t* b) {
    asm volatile("mma.sync.aligned.m16n8k16.row.col.f32.f16.f16.f32 "
        "{%0,%1,%2,%3}, {%4,%5,%6,%7}, {%8,%9}, {%0,%1,%2,%3};"
        : "+f"(c[0]), "+f"(c[1]), "+f"(c[2]), "+f"(c[3])
        : "r"(a[0]), "r"(a[1]), "r"(a[2]), "r"(a[3]), "r"(b[0]), "r"(b[1]));
}

// pack x (low half) and y (high half) into f16x2, plus residual pack
__device__ __forceinline__ void pack_hilo(float x, float y, uint32_t& hi, uint32_t& lo) {
    __half hx = __float2half_rn(x), hy = __float2half_rn(y);
    float rx = x - __half2float(hx), ry = y - __half2float(hy);
    __half lx = __float2half_rn(rx), ly = __float2half_rn(ry);
    union { __half2 h2; uint32_t u; } H, L;
    H.h2 = __halves2half2(hx, hy);
    L.h2 = __halves2half2(lx, ly);
    hi = H.u; lo = L.u;
}

// fast 2^x on FMA pipe (x <= ~0, clamped)
__device__ __forceinline__ float fexp2(float x) {
    x = fmaxf(x, -126.0f);
    int e = __float2int_rn(x);
    float f = x - (float)e;
    float p = 0.0018775767f;
    p = fmaf(p, f, 0.0089893397f);
    p = fmaf(p, f, 0.0558040221f);
    p = fmaf(p, f, 0.2402264923f);
    p = fmaf(p, f, 0.6931471825f);
    p = fmaf(p, f, 1.0f);
    return __int_as_float(__float_as_int(p) + (e << 23));
}

__device__ __forceinline__ void split_f16(float v, __half* hi, __half* lo) {
    __half h = __float2half_rn(v);
    *hi = h;
    *lo = __float2half_rn(v - __half2float(h));
}

// ---------------------------------------------------------------------------
// fp32 -> fp16 hi/lo split (no transpose)
// ---------------------------------------------------------------------------
__global__ void conv_split_kernel(const float* __restrict__ src,
                                  __half* __restrict__ hi,
                                  __half* __restrict__ lo)
{
    int i = blockIdx.x * 256 + threadIdx.x;
    float4 v = ((const float4*)src)[i];
    float f[4] = {v.x, v.y, v.z, v.w};
    union { uint2 u; __half b[4]; } H, L;
    #pragma unroll
    for (int j = 0; j < 4; ++j) split_f16(f[j], &H.b[j], &L.b[j]);
    ((uint2*)hi)[i] = H.u;
    ((uint2*)lo)[i] = L.u;
}

// fp32 W[Kd][Nd] -> single fp16 [Nd][Kd] (transpose); z selects matrix pair
__global__ void transpose_half2_kernel(const float* __restrict__ W0,
                                       __half* __restrict__ O0,
                                       const float* __restrict__ W1,
                                       __half* __restrict__ O1,
                                       int Kd, int Nd)
{
    __shared__ float t[32][33];
    const float* W = blockIdx.z ? W1 : W0;
    __half* out    = blockIdx.z ? O1 : O0;
    int bn = blockIdx.x * 32;
    int bk = blockIdx.y * 32;
    int x = threadIdx.x, y = threadIdx.y;   // (32, 8)
    #pragma unroll
    for (int i = 0; i < 32; i += 8)
        t[y + i][x] = W[(size_t)(bk + y + i) * Nd + bn + x];
    __syncthreads();
    #pragma unroll
    for (int i = 0; i < 32; i += 8)
        out[(size_t)(bn + y + i) * Kd + bk + x] = __float2half_rn(t[x][y + i]);
}

// ---------------------------------------------------------------------------
// mma.sync GEMM: C = (Ah+Al) @ Bh^T, 2 products. 128x128 tile, K-chunks of 32.
// ---------------------------------------------------------------------------
#define TILE_B   10240              // 128*80
#define BUF_B    (3*TILE_B)         // 30720
#define GEMM_SMEM (2*BUF_B)         // 61440

__device__ __forceinline__ void load_tile_async(uint32_t sdst,
                                                const __half* g,
                                                int ldk, int tid)
{
    int r   = tid >> 2;
    int seg = tid & 3;
    #pragma unroll
    for (int h = 0; h < 2; ++h) {
        int row = r + h * 64;
        cp16(sdst + row * 80 + seg * 16, g + (size_t)row * ldk + seg * 8);
    }
}

__device__ __forceinline__ void gemm_body(
    uint32_t sb,
    const __half* Ahi, const __half* Alo, const __half* Bh,
    float* C, int N, int K, int tid)
{
    const int lane = tid & 31, wid = tid >> 5;
    const int wm = wid & 1, wn = wid >> 1;

    float acc[4][4][4];
    #pragma unroll
    for (int mi = 0; mi < 4; ++mi)
        #pragma unroll
        for (int ni = 0; ni < 4; ++ni)
            #pragma unroll
            for (int q = 0; q < 4; ++q) acc[mi][ni][q] = 0.f;

    const int T = K / 32;
    load_tile_async(sb,            Ahi, K, tid);
    load_tile_async(sb +   TILE_B, Alo, K, tid);
    load_tile_async(sb + 2*TILE_B, Bh,  K, tid);
    CP_COMMIT();

    const uint32_t a_lane_off = (uint32_t)((lane & 15) * 80 + (lane >> 4) * 16);
    const uint32_t b_lane_off = (uint32_t)((lane & 7) * 80 + ((lane >> 3) & 1) * 16);

    for (int kt = 0; kt < T; ++kt) {
        if (kt + 1 < T) {
            uint32_t nb = sb + ((kt + 1) & 1) * BUF_B;
            int k0 = (kt + 1) * 32;
            load_tile_async(nb,            Ahi + k0, K, tid);
            load_tile_async(nb +   TILE_B, Alo + k0, K, tid);
            load_tile_async(nb + 2*TILE_B, Bh  + k0, K, tid);
            CP_COMMIT();
            CP_WAIT(1);
        } else {
            CP_WAIT(0);
        }
        __syncthreads();

        uint32_t buf = sb + (kt & 1) * BUF_B;
        #pragma unroll
        for (int ks = 0; ks < 2; ++ks) {
            uint32_t ah[4][4], al[4][4], bh[4][2];
            uint32_t abase = buf + wm * (64 * 80) + a_lane_off + ks * 32;
            #pragma unroll
            for (int mi = 0; mi < 4; ++mi) {
                ldm_x4(ah[mi], abase + mi * (16 * 80));
                ldm_x4(al[mi], abase + TILE_B + mi * (16 * 80));
            }
            uint32_t bbase = buf + 2*TILE_B + wn * (32 * 80) + b_lane_off + ks * 32;
            #pragma unroll
            for (int ni = 0; ni < 4; ++ni)
                ldm_x2(bh[ni], bbase + ni * (8 * 80));
            #pragma unroll
            for (int mi = 0; mi < 4; ++mi)
                #pragma unroll
                for (int ni = 0; ni < 4; ++ni) {
                    mma_f16(acc[mi][ni], ah[mi], bh[ni]);
                    mma_f16(acc[mi][ni], al[mi], bh[ni]);
                }
        }
        __syncthreads();
    }

    #pragma unroll
    for (int mi = 0; mi < 4; ++mi) {
        int row = wm * 64 + mi * 16 + (lane >> 2);
        #pragma unroll
        for (int ni = 0; ni < 4; ++ni) {
            int col = wn * 32 + ni * 8 + (lane & 3) * 2;
            *(float2*)&C[(size_t)row * N + col] =
                make_float2(acc[mi][ni][0], acc[mi][ni][1]);
            *(float2*)&C[(size_t)(row + 8) * N + col] =
                make_float2(acc[mi][ni][2], acc[mi][ni][3]);
        }
    }
}

__global__ __launch_bounds__(256, 1)
void qkv_gemm_kernel(const __half* __restrict__ Ahi,
                     const __half* __restrict__ Alo,
                     const __half* __restrict__ Wq,
                     const __half* __restrict__ Wk,
                     const __half* __restrict__ Wv,
                     float* __restrict__ Cq, float* __restrict__ Ck,
                     float* __restrict__ Cv)
{
    extern __shared__ char smp[];
    uint32_t sb = smem_to_u32(smp);
    const int nb = blockIdx.x;
    const int bm = blockIdx.y * 128;
    const __half* Bh;
    float* C;
    int N, bn;
    if (nb < 16)      { Bh = Wq; C = Cq; N = HID_; bn = nb * 128; }
    else if (nb < 20) { Bh = Wk; C = Ck; N = KVD_; bn = (nb - 16) * 128; }
    else              { Bh = Wv; C = Cv; N = KVD_; bn = (nb - 20) * 128; }
    gemm_body(sb,
              Ahi + (size_t)bm * HID_, Alo + (size_t)bm * HID_,
              Bh + (size_t)bn * HID_,
              C + (size_t)bm * N + bn, N, HID_, threadIdx.x);
}

__global__ __launch_bounds__(256, 1)
void gemm_mma_kernel(const __half* __restrict__ Ahi,
                     const __half* __restrict__ Alo,
                     const __half* __restrict__ Bh,
                     float* __restrict__ C, int N, int K)
{
    extern __shared__ char smp[];
    uint32_t sb = smem_to_u32(smp);
    const int bm = blockIdx.y * 128, bn = blockIdx.x * 128;
    gemm_body(sb,
              Ahi + (size_t)bm * K, Alo + (size_t)bm * K,
              Bh + (size_t)bn * K,
              C + (size_t)bm * N + bn, N, K, threadIdx.x);
}

// ---------------------------------------------------------------------------
// RoPE (pure fp32)
// ---------------------------------------------------------------------------
__device__ __forceinline__ void rope_pair(float x1, float x2, int pos, int d,
                                          float& o1, float& o2)
{
    float inv = exp2f((float)d * (-13.287712379549449f / 64.0f));
    float ang = (float)pos * inv;
    float sn, cs;
    sincosf(ang, &sn, &cs);
    o1 = x1 * cs - x2 * sn;
    o2 = x1 * sn + x2 * cs;
}

__global__ void rope_q_kernel(const int* __restrict__ positions,
                              __half* __restrict__ qh,
                              __half* __restrict__ ql)
{
    int idx = blockIdx.x * blockDim.x + threadIdx.x;   // NH*S*64
    int d = idx & 63;
    int s = (idx >> 6) & (S_ - 1);
    int h = idx >> 17;
    size_t base = (size_t)s * HID_ + h * HD_;
    float x1 = g_q[base + d], x2 = g_q[base + d + 64];
    float o1, o2;
    rope_pair(x1, x2, positions[s], d, o1, o2);
    o1 *= SCL_LOG2E; o2 *= SCL_LOG2E;
    split_f16(o1, &qh[base + d],      &ql[base + d]);
    split_f16(o2, &qh[base + d + 64], &ql[base + d + 64]);
}

__global__ void rope_k_kernel(const int* __restrict__ positions,
                              float* __restrict__ kout,
                              __half* __restrict__ kb)
{
    int idx = blockIdx.x * blockDim.x + threadIdx.x;   // NKV*S*64
    int d  = idx & 63;
    int s  = (idx >> 6) & (S_ - 1);
    int kv = idx >> 17;
    size_t src = (size_t)s * KVD_ + kv * HD_;
    float x1 = g_k[src + d], x2 = g_k[src + d + 64];
    float o1, o2;
    rope_pair(x1, x2, positions[s], d, o1, o2);
    #pragma unroll
    for (int g = 0; g < GRP_; ++g) {
        size_t dst = ((size_t)(kv * GRP_ + g) * S_ + s) * HD_;
        kout[dst + d] = o1; kout[dst + d + 64] = o2;
    }
    size_t cb = ((size_t)kv * S_ + s) * HD_;
    kb[cb + d]      = __float2half_rn(o1);
    kb[cb + d + 64] = __float2half_rn(o2);
}

__global__ void copy_v_kernel(float* __restrict__ vout,
                              __half* __restrict__ vb)
{
    int idx = blockIdx.x * blockDim.x + threadIdx.x;   // NKV*S*32 float4s
    int d4 = idx & 31;
    int s  = (idx >> 5) & (S_ - 1);
    int kv = idx >> 16;
    float4 v = *(const float4*)&g_v[(size_t)s * KVD_ + kv * HD_ + d4 * 4];
    #pragma unroll
    for (int g = 0; g < GRP_; ++g)
        *(float4*)&vout[((size_t)(kv * GRP_ + g) * S_ + s) * HD_ + d4 * 4] = v;
    size_t cb = ((size_t)kv * S_ + s) * HD_ + d4 * 4;
    float f[4] = {v.x, v.y, v.z, v.w};
    union { uint2 u; __half b[4]; } H;
    #pragma unroll
    for (int j = 0; j < 4; ++j) H.b[j] = __float2half_rn(f[j]);
    *(uint2*)&vb[cb] = H.u;
}

// ---------------------------------------------------------------------------
// Tensor-core flash attention: BQ=128, BK=64, HD=128, 8 warps.
// QK: (Qh+Ql)*Kh (2 products). PV: (Ph+Pl)*Vh (2 products).
// ---------------------------------------------------------------------------
#define FSTR  272                   // bytes per smem row (256 + 16 pad)
#define FQ_B  (128*FSTR)            // 34816
#define FKV_B (64*FSTR)             // 17408
#define FLASH_SMEM (2*FQ_B + 4*FKV_B)  // 139264

__global__ __launch_bounds__(256, 1)
void flash_tc_kernel(const __half* __restrict__ qhp,
                     const __half* __restrict__ qlp,
                     const __half* __restrict__ khp,
                     const __half* __restrict__ vhp,
                     __half* __restrict__ ath,
                     __half* __restrict__ atl)
{
    extern __shared__ char smp[];
    const uint32_t sb = smem_to_u32(smp);
    const int tid = threadIdx.x, lane = tid & 31, w = tid >> 5;
    const int qb = 15 - blockIdx.x, h = blockIdx.y, kv = h >> 2;
    const int q0 = qb * 128;

    const uint32_t sQh = sb, sQl = sb + FQ_B;
    const uint32_t sKV = sb + 2 * FQ_B;   // per buffer: [Kh | Vh]

    {
        const __half* srch = qhp + (size_t)q0 * HID_ + h * HD_;
        const __half* srcl = qlp + (size_t)q0 * HID_ + h * HD_;
        #pragma unroll
        for (int c = tid; c < 2048; c += 256) {
            int r = c >> 4, seg = c & 15;
            cp16(sQh + r * FSTR + seg * 16, srch + (size_t)r * HID_ + seg * 8);
            cp16(sQl + r * FSTR + seg * 16, srcl + (size_t)r * HID_ + seg * 8);
        }
    }
    const __half* kb = khp + (size_t)kv * S_ * HD_;
    const __half* vb = vhp + (size_t)kv * S_ * HD_;

    auto load_kv = [&](int kt, uint32_t buf) {
        #pragma unroll
        for (int c = tid; c < 1024; c += 256) {
            int r = c >> 4, seg = c & 15;
            size_t g = (size_t)(kt * 64 + r) * HD_ + seg * 8;
            uint32_t so = r * FSTR + seg * 16;
            cp16(buf + so,         kb + g);
            cp16(buf + FKV_B + so, vb + g);
        }
    };
    load_kv(0, sKV);
    CP_COMMIT();

    float o[16][4];
    #pragma unroll
    for (int j = 0; j < 16; ++j)
        #pragma unroll
        for (int q = 0; q < 4; ++q) o[j][q] = 0.f;
    float m0 = -1e30f, m1 = -1e30f, l0 = 0.f, l1 = 0.f;

    const int last = 2 * qb + 1;
    const uint32_t a_off  = (lane & 15) * FSTR + (lane >> 4) * 16;
    const uint32_t bk_off = (lane & 7) * FSTR + ((lane >> 3) & 1) * 16;
    const uint32_t bv_off = (lane & 15) * FSTR;
    const int r0 = q0 + w * 16 + (lane >> 2);

    for (int kt = 0; kt <= last; ++kt) {
        if (kt < last) {
            load_kv(kt + 1, sKV + ((kt + 1) & 1) * 2 * FKV_B);
            CP_COMMIT();
            CP_WAIT(1);
        } else {
            CP_WAIT(0);
        }
        __syncthreads();

        const uint32_t bK = sKV + (kt & 1) * 2 * FKV_B;
        const uint32_t bV = bK + FKV_B;

        // ---- scores S = (Qh+Ql) Kh^T ----
        float s[8][4];
        #pragma unroll
        for (int j = 0; j < 8; ++j)
            #pragma unroll
            for (int q = 0; q < 4; ++q) s[j][q] = 0.f;

        #pragma unroll
        for (int ks = 0; ks < 8; ++ks) {
            uint32_t ah[4], al[4];
            ldm_x4(ah, sQh + w * (16 * FSTR) + a_off + ks * 32);
            ldm_x4(al, sQl + w * (16 * FSTR) + a_off + ks * 32);
            #pragma unroll
            for (int j = 0; j < 8; ++j) {
                uint32_t bh2[2];
                ldm_x2(bh2, bK + j * (8 * FSTR) + bk_off + ks * 32);
                mma_f16(s[j], ah, bh2);
                mma_f16(s[j], al, bh2);
            }
        }

        // ---- causal mask ----
        if (kt >= 2 * qb) {
            #pragma unroll
            for (int j = 0; j < 8; ++j) {
                int col = kt * 64 + j * 8 + (lane & 3) * 2;
                if (col     > r0)     s[j][0] = -3e4f;
                if (col + 1 > r0)     s[j][1] = -3e4f;
                if (col     > r0 + 8) s[j][2] = -3e4f;
                if (col + 1 > r0 + 8) s[j][3] = -3e4f;
            }
        }

        // ---- row max (quad reduce) ----
        float mx0 = -3e4f, mx1 = -3e4f;
        #pragma unroll
        for (int j = 0; j < 8; ++j) {
            mx0 = fmaxf(mx0, fmaxf(s[j][0], s[j][1]));
            mx1 = fmaxf(mx1, fmaxf(s[j][2], s[j][3]));
        }
        mx0 = fmaxf(mx0, __shfl_xor_sync(0xffffffffu, mx0, 1));
        mx0 = fmaxf(mx0, __shfl_xor_sync(0xffffffffu, mx0, 2));
        mx1 = fmaxf(mx1, __shfl_xor_sync(0xffffffffu, mx1, 1));
        mx1 = fmaxf(mx1, __shfl_xor_sync(0xffffffffu, mx1, 2));

        const float mn0 = fmaxf(m0, mx0), mn1 = fmaxf(m1, mx1);
        const float al0 = fexp2(m0 - mn0), al1 = fexp2(m1 - mn1);
        m0 = mn0; m1 = mn1;

        // ---- exp + row sum ----
        float sum0 = 0.f, sum1 = 0.f;
        #pragma unroll
        for (int j = 0; j < 8; ++j) {
            s[j][0] = fexp2(s[j][0] - mn0);
            s[j][1] = fexp2(s[j][1] - mn0);
            s[j][2] = fexp2(s[j][2] - mn1);
            s[j][3] = fexp2(s[j][3] - mn1);
            sum0 += s[j][0] + s[j][1];
            sum1 += s[j][2] + s[j][3];
        }
        sum0 += __shfl_xor_sync(0xffffffffu, sum0, 1);
        sum0 += __shfl_xor_sync(0xffffffffu, sum0, 2);
        sum1 += __shfl_xor_sync(0xffffffffu, sum1, 1);
        sum1 += __shfl_xor_sync(0xffffffffu, sum1, 2);
        l0 = l0 * al0 + sum0;
        l1 = l1 * al1 + sum1;

        // ---- rescale O ----
        #pragma unroll
        for (int j = 0; j < 16; ++j) {
            o[j][0] *= al0; o[j][1] *= al0;
            o[j][2] *= al1; o[j][3] *= al1;
        }

        // ---- O += (Ph+Pl) Vh (2 products) ----
        #pragma unroll
        for (int pk = 0; pk < 4; ++pk) {
            uint32_t phi[4], plo[4];
            pack_hilo(s[2*pk][0],   s[2*pk][1],   phi[0], plo[0]);
            pack_hilo(s[2*pk][2],   s[2*pk][3],   phi[1], plo[1]);
            pack_hilo(s[2*pk+1][0], s[2*pk+1][1], phi[2], plo[2]);
            pack_hilo(s[2*pk+1][2], s[2*pk+1][3], phi[3], plo[3]);
            #pragma unroll
            for (int j = 0; j < 16; ++j) {
                uint32_t bh2[2];
                ldm_x2t(bh2, bV + pk * (16 * FSTR) + bv_off + j * 16);
                mma_f16(o[j], phi, bh2);
                mma_f16(o[j], plo, bh2);
            }
        }
        __syncthreads();
    }

    // ---- epilogue: normalize, split to fp16 hi/lo ----
    const float inv0 = 1.f / l0, inv1 = 1.f / l1;
    #pragma unroll
    for (int j = 0; j < 16; ++j) {
        int col = j * 8 + (lane & 3) * 2;
        uint32_t hi, lo;
        pack_hilo(o[j][0] * inv0, o[j][1] * inv0, hi, lo);
        size_t off0 = (size_t)r0 * HID_ + h * HD_ + col;
        *(uint32_t*)&ath[off0] = hi;
        *(uint32_t*)&atl[off0] = lo;
        pack_hilo(o[j][2] * inv1, o[j][3] * inv1, hi, lo);
        size_t off1 = (size_t)(r0 + 8) * HID_ + h * HD_ + col;
        *(uint32_t*)&ath[off1] = hi;
        *(uint32_t*)&atl[off1] = lo;
    }
}

// ---------------------------------------------------------------------------
extern "C" void kernel_launch(void* const* d_in, const int* in_sizes, int n_in,
                              void* d_out, int out_size)
{
    const float* hs  = (const float*)d_in[0];
    const int*   pos = (const int*)  d_in[1];
    const float* Wq  = (const float*)d_in[3];
    const float* Wk  = (const float*)d_in[4];
    const float* Wv  = (const float*)d_in[5];
    const float* Wo  = (const float*)d_in[6];

    float* out  = (float*)d_out;                       // [S, HID]
    float* kout = out  + (size_t)S_ * HID_;            // [NH, S, HD] (repeated)
    float* vout = kout + (size_t)NH_ * S_ * HD_;       // [NH, S, HD] (repeated)

    float *qp, *kp, *vp;
    cudaGetSymbolAddress((void**)&qp, g_q);
    cudaGetSymbolAddress((void**)&kp, g_k);
    cudaGetSymbolAddress((void**)&vp, g_v);
    __half *hsh, *hsl, *wq, *wk, *wv, *wo, *ath, *atl;
    __half *qbh, *qbl, *kb, *vb;
    cudaGetSymbolAddress((void**)&hsh, g_hs_hi); cudaGetSymbolAddress((void**)&hsl, g_hs_lo);
    cudaGetSymbolAddress((void**)&wq, g_wq);
    cudaGetSymbolAddress((void**)&wk, g_wk);
    cudaGetSymbolAddress((void**)&wv, g_wv);
    cudaGetSymbolAddress((void**)&wo, g_wo);
    cudaGetSymbolAddress((void**)&ath, g_at_hi); cudaGetSymbolAddress((void**)&atl, g_at_lo);
    cudaGetSymbolAddress((void**)&qbh, g_qb_hi); cudaGetSymbolAddress((void**)&qbl, g_qb_lo);
    cudaGetSymbolAddress((void**)&kb, g_kb);
    cudaGetSymbolAddress((void**)&vb, g_vb);

    cudaFuncSetAttribute(qkv_gemm_kernel,
                         cudaFuncAttributeMaxDynamicSharedMemorySize, GEMM_SMEM);
    cudaFuncSetAttribute(gemm_mma_kernel,
                         cudaFuncAttributeMaxDynamicSharedMemorySize, GEMM_SMEM);
    cudaFuncSetAttribute(flash_tc_kernel,
                         cudaFuncAttributeMaxDynamicSharedMemorySize, FLASH_SMEM);

    // input conversions (transposes batched: 2 launches)
    conv_split_kernel<<<(S_*HID_/4)/256, 256>>>(hs, hsh, hsl);
    transpose_half2_kernel<<<dim3(HID_/32, HID_/32, 2), dim3(32,8)>>>(
        Wq, wq, Wo, wo, HID_, HID_);
    transpose_half2_kernel<<<dim3(KVD_/32, HID_/32, 2), dim3(32,8)>>>(
        Wk, wk, Wv, wv, HID_, KVD_);

    // fused QKV projection (2-product fp16)
    qkv_gemm_kernel<<<dim3(24, S_/128), 256, GEMM_SMEM>>>(
        hsh, hsl, wq, wk, wv, qp, kp, vp);

    // rope + layout (+ compact fp16 copies for flash)
    rope_q_kernel<<<(NH_*S_*64)/256, 256>>>(pos, qbh, qbl);
    rope_k_kernel<<<(NKV_*S_*64)/256, 256>>>(pos, kout, kb);
    copy_v_kernel<<<(NKV_*S_*32)/256, 256>>>(vout, vb);

    // attention (tensor core flash) -> fp16 hi/lo
    flash_tc_kernel<<<dim3(16, NH_), 256, FLASH_SMEM>>>(
        qbh, qbl, kb, vb, ath, atl);

    // output projection (2-product fp16)
    gemm_mma_kernel<<<dim3(HID_/128, S_/128), 256, GEMM_SMEM>>>(
        ath, atl, wo, out, HID_, HID_);
}

// round 8
// speedup vs baseline: 6.0588x; 1.1054x over previous
#include <cuda_runtime.h>
#include <cuda_fp16.h>
#include <math.h>
#include <stdint.h>

#define S_   2048
#define HID_ 2048
#define NH_  16
#define NKV_ 4
#define GRP_ (NH_/NKV_)   // 4
#define HD_  128
#define KVD_ (NKV_*HD_)   // 512

// scale * log2(e), folded into Q at rope time
#define SCL_LOG2E 0.12751744f

// ---------------------------------------------------------------------------
// scratch (allocation-free: __device__ globals)
// ---------------------------------------------------------------------------
__device__ float g_q  [S_*HID_];   // Q projection (fp32)
__device__ float g_k  [S_*KVD_];   // K projection pre-rope
__device__ float g_v  [S_*KVD_];   // V projection

__device__ __half g_hs_hi[S_*HID_],  g_hs_lo[S_*HID_];    // hidden [m][k] (A split)
__device__ __half g_wq[HID_*HID_];                        // weights [n][k] single fp16
__device__ __half g_wk[KVD_*HID_];
__device__ __half g_wv[KVD_*HID_];
__device__ __half g_wo[HID_*HID_];
__device__ __half g_at_hi[S_*HID_],  g_at_lo[S_*HID_];    // attn out [m][k] (A split)

__device__ __half g_qb_hi[S_*HID_],  g_qb_lo[S_*HID_];    // roped Q*scl (A split)
__device__ __half g_kb[NKV_*S_*HD_];                      // K single [kv][s][d]
__device__ __half g_vb[NKV_*S_*HD_];                      // V single [kv][s][d]

// ---------------------------------------------------------------------------
// PTX helpers (plain sm_103-safe)
// ---------------------------------------------------------------------------
__device__ __forceinline__ uint32_t smem_to_u32(const void* p) {
    uint32_t a;
    asm("{ .reg .u64 t; cvta.to.shared.u64 t, %1; cvt.u32.u64 %0, t; }"
        : "=r"(a) : "l"(p));
    return a;
}
__device__ __forceinline__ void cp16(uint32_t dst, const void* src) {
    asm volatile("cp.async.cg.shared.global [%0], [%1], 16;" :: "r"(dst), "l"(src));
}
#define CP_COMMIT() asm volatile("cp.async.commit_group;" ::: "memory")
#define CP_WAIT(n)  asm volatile("cp.async.wait_group %0;" :: "n"(n) : "memory")

__device__ __forceinline__ void ldm_x4(uint32_t* r, uint32_t addr) {
    asm volatile("ldmatrix.sync.aligned.m8n8.x4.shared.b16 {%0,%1,%2,%3}, [%4];"
        : "=r"(r[0]), "=r"(r[1]), "=r"(r[2]), "=r"(r[3]) : "r"(addr));
}
__device__ __forceinline__ void ldm_x2(uint32_t* r, uint32_t addr) {
    asm volatile("ldmatrix.sync.aligned.m8n8.x2.shared.b16 {%0,%1}, [%2];"
        : "=r"(r[0]), "=r"(r[1]) : "r"(addr));
}
__device__ __forceinline__ void ldm_x2t(uint32_t* r, uint32_t addr) {
    asm volatile("ldmatrix.sync.aligned.m8n8.x2.trans.shared.b16 {%0,%1}, [%2];"
        : "=r"(r[0]), "=r"(r[1]) : "r"(addr));
}
__device__ __forceinline__ void mma_f16(float* c, const uint32_t* a, const uint32_t* b) {
    asm volatile("mma.sync.aligned.m16n8k16.row.col.f32.f16.f16.f32 "
        "{%0,%1,%2,%3}, {%4,%5,%6,%7}, {%8,%9}, {%0,%1,%2,%3};"
        : "+f"(c[0]), "+f"(c[1]), "+f"(c[2]), "+f"(c[3])
        : "r"(a[0]), "r"(a[1]), "r"(a[2]), "r"(a[3]), "r"(b[0]), "r"(b[1]));
}

// pack x (low half) and y (high half) into f16x2, plus residual pack
__device__ __forceinline__ void pack_hilo(float x, float y, uint32_t& hi, uint32_t& lo) {
    __half hx = __float2half_rn(x), hy = __float2half_rn(y);
    float rx = x - __half2float(hx), ry = y - __half2float(hy);
    __half lx = __float2half_rn(rx), ly = __float2half_rn(ry);
    union { __half2 h2; uint32_t u; } H, L;
    H.h2 = __halves2half2(hx, hy);
    L.h2 = __halves2half2(lx, ly);
    hi = H.u; lo = L.u;
}

// fast 2^x on FMA pipe (x <= ~0, clamped)
__device__ __forceinline__ float fexp2(float x) {
    x = fmaxf(x, -126.0f);
    int e = __float2int_rn(x);
    float f = x - (float)e;
    float p = 0.0018775767f;
    p = fmaf(p, f, 0.0089893397f);
    p = fmaf(p, f, 0.0558040221f);
    p = fmaf(p, f, 0.2402264923f);
    p = fmaf(p, f, 0.6931471825f);
    p = fmaf(p, f, 1.0f);
    return __int_as_float(__float_as_int(p) + (e << 23));
}

__device__ __forceinline__ void split_f16(float v, __half* hi, __half* lo) {
    __half h = __float2half_rn(v);
    *hi = h;
    *lo = __float2half_rn(v - __half2float(h));
}

// ---------------------------------------------------------------------------
// fp32 -> fp16 hi/lo split (no transpose)
// ---------------------------------------------------------------------------
__global__ void conv_split_kernel(const float* __restrict__ src,
                                  __half* __restrict__ hi,
                                  __half* __restrict__ lo)
{
    int i = blockIdx.x * 256 + threadIdx.x;
    float4 v = ((const float4*)src)[i];
    float f[4] = {v.x, v.y, v.z, v.w};
    union { uint2 u; __half b[4]; } H, L;
    #pragma unroll
    for (int j = 0; j < 4; ++j) split_f16(f[j], &H.b[j], &L.b[j]);
    ((uint2*)hi)[i] = H.u;
    ((uint2*)lo)[i] = L.u;
}

// fp32 W[Kd][Nd] -> single fp16 [Nd][Kd] (transpose); z selects matrix pair
__global__ void transpose_half2_kernel(const float* __restrict__ W0,
                                       __half* __restrict__ O0,
                                       const float* __restrict__ W1,
                                       __half* __restrict__ O1,
                                       int Kd, int Nd)
{
    __shared__ float t[32][33];
    const float* W = blockIdx.z ? W1 : W0;
    __half* out    = blockIdx.z ? O1 : O0;
    int bn = blockIdx.x * 32;
    int bk = blockIdx.y * 32;
    int x = threadIdx.x, y = threadIdx.y;   // (32, 8)
    #pragma unroll
    for (int i = 0; i < 32; i += 8)
        t[y + i][x] = W[(size_t)(bk + y + i) * Nd + bn + x];
    __syncthreads();
    #pragma unroll
    for (int i = 0; i < 32; i += 8)
        out[(size_t)(bn + y + i) * Kd + bk + x] = __float2half_rn(t[x][y + i]);
}

// ---------------------------------------------------------------------------
// mma.sync GEMM: C = (Ah+Al) @ Bh^T, 2 products. 128x128 tile, K-chunks of 32.
// 3-stage cp.async pipeline, ONE __syncthreads per K-iter, 2 CTAs/SM.
// ---------------------------------------------------------------------------
#define TILE_B   10240              // 128*80
#define BUF_B    (3*TILE_B)         // 30720 per stage
#define GEMM_SMEM (3*BUF_B)         // 92160 (3 stages)

__device__ __forceinline__ void load_tile_async(uint32_t sdst,
                                                const __half* g,
                                                int ldk, int tid)
{
    int r   = tid >> 2;
    int seg = tid & 3;
    #pragma unroll
    for (int h = 0; h < 2; ++h) {
        int row = r + h * 64;
        cp16(sdst + row * 80 + seg * 16, g + (size_t)row * ldk + seg * 8);
    }
}

__device__ __forceinline__ void load_stage(uint32_t buf,
                                           const __half* Ahi, const __half* Alo,
                                           const __half* Bh, int k0, int K, int tid)
{
    load_tile_async(buf,            Ahi + k0, K, tid);
    load_tile_async(buf +   TILE_B, Alo + k0, K, tid);
    load_tile_async(buf + 2*TILE_B, Bh  + k0, K, tid);
}

__device__ __forceinline__ void gemm_body(
    uint32_t sb,
    const __half* Ahi, const __half* Alo, const __half* Bh,
    float* C, int N, int K, int tid)
{
    const int lane = tid & 31, wid = tid >> 5;
    const int wm = wid & 1, wn = wid >> 1;

    float acc[4][4][4];
    #pragma unroll
    for (int mi = 0; mi < 4; ++mi)
        #pragma unroll
        for (int ni = 0; ni < 4; ++ni)
            #pragma unroll
            for (int q = 0; q < 4; ++q) acc[mi][ni][q] = 0.f;

    const int T = K / 32;
    // prologue: stages 0, 1
    load_stage(sb,         Ahi, Alo, Bh, 0,  K, tid);
    CP_COMMIT();
    load_stage(sb + BUF_B, Ahi, Alo, Bh, 32, K, tid);
    CP_COMMIT();

    const uint32_t a_lane_off = (uint32_t)((lane & 15) * 80 + (lane >> 4) * 16);
    const uint32_t b_lane_off = (uint32_t)((lane & 7) * 80 + ((lane >> 3) & 1) * 16);

    int bufidx = 0;
    for (int kt = 0; kt < T; ++kt) {
        CP_WAIT(1);
        __syncthreads();

        // prefetch kt+2 into the stage freed by compute(kt-1)
        if (kt + 2 < T) {
            int nbi = bufidx + 2; if (nbi >= 3) nbi -= 3;
            load_stage(sb + nbi * BUF_B, Ahi, Alo, Bh, (kt + 2) * 32, K, tid);
            CP_COMMIT();
        }

        uint32_t buf = sb + bufidx * BUF_B;
        #pragma unroll
        for (int ks = 0; ks < 2; ++ks) {
            uint32_t ah[4][4], al[4][4], bh[4][2];
            uint32_t abase = buf + wm * (64 * 80) + a_lane_off + ks * 32;
            #pragma unroll
            for (int mi = 0; mi < 4; ++mi) {
                ldm_x4(ah[mi], abase + mi * (16 * 80));
                ldm_x4(al[mi], abase + TILE_B + mi * (16 * 80));
            }
            uint32_t bbase = buf + 2*TILE_B + wn * (32 * 80) + b_lane_off + ks * 32;
            #pragma unroll
            for (int ni = 0; ni < 4; ++ni)
                ldm_x2(bh[ni], bbase + ni * (8 * 80));
            #pragma unroll
            for (int mi = 0; mi < 4; ++mi)
                #pragma unroll
                for (int ni = 0; ni < 4; ++ni) {
                    mma_f16(acc[mi][ni], ah[mi], bh[ni]);
                    mma_f16(acc[mi][ni], al[mi], bh[ni]);
                }
        }
        if (++bufidx == 3) bufidx = 0;
    }

    #pragma unroll
    for (int mi = 0; mi < 4; ++mi) {
        int row = wm * 64 + mi * 16 + (lane >> 2);
        #pragma unroll
        for (int ni = 0; ni < 4; ++ni) {
            int col = wn * 32 + ni * 8 + (lane & 3) * 2;
            *(float2*)&C[(size_t)row * N + col] =
                make_float2(acc[mi][ni][0], acc[mi][ni][1]);
            *(float2*)&C[(size_t)(row + 8) * N + col] =
                make_float2(acc[mi][ni][2], acc[mi][ni][3]);
        }
    }
}

__global__ __launch_bounds__(256, 2)
void qkv_gemm_kernel(const __half* __restrict__ Ahi,
                     const __half* __restrict__ Alo,
                     const __half* __restrict__ Wq,
                     const __half* __restrict__ Wk,
                     const __half* __restrict__ Wv,
                     float* __restrict__ Cq, float* __restrict__ Ck,
                     float* __restrict__ Cv)
{
    extern __shared__ char smp[];
    uint32_t sb = smem_to_u32(smp);
    const int nb = blockIdx.x;
    const int bm = blockIdx.y * 128;
    const __half* Bh;
    float* C;
    int N, bn;
    if (nb < 16)      { Bh = Wq; C = Cq; N = HID_; bn = nb * 128; }
    else if (nb < 20) { Bh = Wk; C = Ck; N = KVD_; bn = (nb - 16) * 128; }
    else              { Bh = Wv; C = Cv; N = KVD_; bn = (nb - 20) * 128; }
    gemm_body(sb,
              Ahi + (size_t)bm * HID_, Alo + (size_t)bm * HID_,
              Bh + (size_t)bn * HID_,
              C + (size_t)bm * N + bn, N, HID_, threadIdx.x);
}

__global__ __launch_bounds__(256, 2)
void gemm_mma_kernel(const __half* __restrict__ Ahi,
                     const __half* __restrict__ Alo,
                     const __half* __restrict__ Bh,
                     float* __restrict__ C, int N, int K)
{
    extern __shared__ char smp[];
    uint32_t sb = smem_to_u32(smp);
    const int bm = blockIdx.y * 128, bn = blockIdx.x * 128;
    gemm_body(sb,
              Ahi + (size_t)bm * K, Alo + (size_t)bm * K,
              Bh + (size_t)bn * K,
              C + (size_t)bm * N + bn, N, K, threadIdx.x);
}

// ---------------------------------------------------------------------------
// RoPE (pure fp32)
// ---------------------------------------------------------------------------
__device__ __forceinline__ void rope_pair(float x1, float x2, int pos, int d,
                                          float& o1, float& o2)
{
    float inv = exp2f((float)d * (-13.287712379549449f / 64.0f));
    float ang = (float)pos * inv;
    float sn, cs;
    sincosf(ang, &sn, &cs);
    o1 = x1 * cs - x2 * sn;
    o2 = x1 * sn + x2 * cs;
}

__global__ void rope_q_kernel(const int* __restrict__ positions,
                              __half* __restrict__ qh,
                              __half* __restrict__ ql)
{
    int idx = blockIdx.x * blockDim.x + threadIdx.x;   // NH*S*64
    int d = idx & 63;
    int s = (idx >> 6) & (S_ - 1);
    int h = idx >> 17;
    size_t base = (size_t)s * HID_ + h * HD_;
    float x1 = g_q[base + d], x2 = g_q[base + d + 64];
    float o1, o2;
    rope_pair(x1, x2, positions[s], d, o1, o2);
    o1 *= SCL_LOG2E; o2 *= SCL_LOG2E;
    split_f16(o1, &qh[base + d],      &ql[base + d]);
    split_f16(o2, &qh[base + d + 64], &ql[base + d + 64]);
}

__global__ void rope_k_kernel(const int* __restrict__ positions,
                              float* __restrict__ kout,
                              __half* __restrict__ kb)
{
    int idx = blockIdx.x * blockDim.x + threadIdx.x;   // NKV*S*64
    int d  = idx & 63;
    int s  = (idx >> 6) & (S_ - 1);
    int kv = idx >> 17;
    size_t src = (size_t)s * KVD_ + kv * HD_;
    float x1 = g_k[src + d], x2 = g_k[src + d + 64];
    float o1, o2;
    rope_pair(x1, x2, positions[s], d, o1, o2);
    #pragma unroll
    for (int g = 0; g < GRP_; ++g) {
        size_t dst = ((size_t)(kv * GRP_ + g) * S_ + s) * HD_;
        kout[dst + d] = o1; kout[dst + d + 64] = o2;
    }
    size_t cb = ((size_t)kv * S_ + s) * HD_;
    kb[cb + d]      = __float2half_rn(o1);
    kb[cb + d + 64] = __float2half_rn(o2);
}

__global__ void copy_v_kernel(float* __restrict__ vout,
                              __half* __restrict__ vb)
{
    int idx = blockIdx.x * blockDim.x + threadIdx.x;   // NKV*S*32 float4s
    int d4 = idx & 31;
    int s  = (idx >> 5) & (S_ - 1);
    int kv = idx >> 16;
    float4 v = *(const float4*)&g_v[(size_t)s * KVD_ + kv * HD_ + d4 * 4];
    #pragma unroll
    for (int g = 0; g < GRP_; ++g)
        *(float4*)&vout[((size_t)(kv * GRP_ + g) * S_ + s) * HD_ + d4 * 4] = v;
    size_t cb = ((size_t)kv * S_ + s) * HD_ + d4 * 4;
    float f[4] = {v.x, v.y, v.z, v.w};
    union { uint2 u; __half b[4]; } H;
    #pragma unroll
    for (int j = 0; j < 4; ++j) H.b[j] = __float2half_rn(f[j]);
    *(uint2*)&vb[cb] = H.u;
}

// ---------------------------------------------------------------------------
// Tensor-core flash attention: BQ=128, BK=64, HD=128, 8 warps.
// QK: (Qh+Ql)*Kh (2 products). PV: (Ph+Pl)*Vh (2 products).
// ---------------------------------------------------------------------------
#define FSTR  272                   // bytes per smem row (256 + 16 pad)
#define FQ_B  (128*FSTR)            // 34816
#define FKV_B (64*FSTR)             // 17408
#define FLASH_SMEM (2*FQ_B + 4*FKV_B)  // 139264

__global__ __launch_bounds__(256, 1)
void flash_tc_kernel(const __half* __restrict__ qhp,
                     const __half* __restrict__ qlp,
                     const __half* __restrict__ khp,
                     const __half* __restrict__ vhp,
                     __half* __restrict__ ath,
                     __half* __restrict__ atl)
{
    extern __shared__ char smp[];
    const uint32_t sb = smem_to_u32(smp);
    const int tid = threadIdx.x, lane = tid & 31, w = tid >> 5;
    const int qb = 15 - blockIdx.x, h = blockIdx.y, kv = h >> 2;
    const int q0 = qb * 128;

    const uint32_t sQh = sb, sQl = sb + FQ_B;
    const uint32_t sKV = sb + 2 * FQ_B;   // per buffer: [Kh | Vh]

    {
        const __half* srch = qhp + (size_t)q0 * HID_ + h * HD_;
        const __half* srcl = qlp + (size_t)q0 * HID_ + h * HD_;
        #pragma unroll
        for (int c = tid; c < 2048; c += 256) {
            int r = c >> 4, seg = c & 15;
            cp16(sQh + r * FSTR + seg * 16, srch + (size_t)r * HID_ + seg * 8);
            cp16(sQl + r * FSTR + seg * 16, srcl + (size_t)r * HID_ + seg * 8);
        }
    }
    const __half* kb = khp + (size_t)kv * S_ * HD_;
    const __half* vb = vhp + (size_t)kv * S_ * HD_;

    auto load_kv = [&](int kt, uint32_t buf) {
        #pragma unroll
        for (int c = tid; c < 1024; c += 256) {
            int r = c >> 4, seg = c & 15;
            size_t g = (size_t)(kt * 64 + r) * HD_ + seg * 8;
            uint32_t so = r * FSTR + seg * 16;
            cp16(buf + so,         kb + g);
            cp16(buf + FKV_B + so, vb + g);
        }
    };
    load_kv(0, sKV);
    CP_COMMIT();

    float o[16][4];
    #pragma unroll
    for (int j = 0; j < 16; ++j)
        #pragma unroll
        for (int q = 0; q < 4; ++q) o[j][q] = 0.f;
    float m0 = -1e30f, m1 = -1e30f, l0 = 0.f, l1 = 0.f;

    const int last = 2 * qb + 1;
    const uint32_t a_off  = (lane & 15) * FSTR + (lane >> 4) * 16;
    const uint32_t bk_off = (lane & 7) * FSTR + ((lane >> 3) & 1) * 16;
    const uint32_t bv_off = (lane & 15) * FSTR;
    const int r0 = q0 + w * 16 + (lane >> 2);

    for (int kt = 0; kt <= last; ++kt) {
        if (kt < last) {
            load_kv(kt + 1, sKV + ((kt + 1) & 1) * 2 * FKV_B);
            CP_COMMIT();
            CP_WAIT(1);
        } else {
            CP_WAIT(0);
        }
        __syncthreads();

        const uint32_t bK = sKV + (kt & 1) * 2 * FKV_B;
        const uint32_t bV = bK + FKV_B;

        // ---- scores S = (Qh+Ql) Kh^T ----
        float s[8][4];
        #pragma unroll
        for (int j = 0; j < 8; ++j)
            #pragma unroll
            for (int q = 0; q < 4; ++q) s[j][q] = 0.f;

        #pragma unroll
        for (int ks = 0; ks < 8; ++ks) {
            uint32_t ah[4], al[4];
            ldm_x4(ah, sQh + w * (16 * FSTR) + a_off + ks * 32);
            ldm_x4(al, sQl + w * (16 * FSTR) + a_off + ks * 32);
            #pragma unroll
            for (int j = 0; j < 8; ++j) {
                uint32_t bh2[2];
                ldm_x2(bh2, bK + j * (8 * FSTR) + bk_off + ks * 32);
                mma_f16(s[j], ah, bh2);
                mma_f16(s[j], al, bh2);
            }
        }

        // ---- causal mask ----
        if (kt >= 2 * qb) {
            #pragma unroll
            for (int j = 0; j < 8; ++j) {
                int col = kt * 64 + j * 8 + (lane & 3) * 2;
                if (col     > r0)     s[j][0] = -3e4f;
                if (col + 1 > r0)     s[j][1] = -3e4f;
                if (col     > r0 + 8) s[j][2] = -3e4f;
                if (col + 1 > r0 + 8) s[j][3] = -3e4f;
            }
        }

        // ---- row max (quad reduce) ----
        float mx0 = -3e4f, mx1 = -3e4f;
        #pragma unroll
        for (int j = 0; j < 8; ++j) {
            mx0 = fmaxf(mx0, fmaxf(s[j][0], s[j][1]));
            mx1 = fmaxf(mx1, fmaxf(s[j][2], s[j][3]));
        }
        mx0 = fmaxf(mx0, __shfl_xor_sync(0xffffffffu, mx0, 1));
        mx0 = fmaxf(mx0, __shfl_xor_sync(0xffffffffu, mx0, 2));
        mx1 = fmaxf(mx1, __shfl_xor_sync(0xffffffffu, mx1, 1));
        mx1 = fmaxf(mx1, __shfl_xor_sync(0xffffffffu, mx1, 2));

        const float mn0 = fmaxf(m0, mx0), mn1 = fmaxf(m1, mx1);
        const float al0 = fexp2(m0 - mn0), al1 = fexp2(m1 - mn1);
        m0 = mn0; m1 = mn1;

        // ---- exp + row sum ----
        float sum0 = 0.f, sum1 = 0.f;
        #pragma unroll
        for (int j = 0; j < 8; ++j) {
            s[j][0] = fexp2(s[j][0] - mn0);
            s[j][1] = fexp2(s[j][1] - mn0);
            s[j][2] = fexp2(s[j][2] - mn1);
            s[j][3] = fexp2(s[j][3] - mn1);
            sum0 += s[j][0] + s[j][1];
            sum1 += s[j][2] + s[j][3];
        }
        sum0 += __shfl_xor_sync(0xffffffffu, sum0, 1);
        sum0 += __shfl_xor_sync(0xffffffffu, sum0, 2);
        sum1 += __shfl_xor_sync(0xffffffffu, sum1, 1);
        sum1 += __shfl_xor_sync(0xffffffffu, sum1, 2);
        l0 = l0 * al0 + sum0;
        l1 = l1 * al1 + sum1;

        // ---- rescale O ----
        #pragma unroll
        for (int j = 0; j < 16; ++j) {
            o[j][0] *= al0; o[j][1] *= al0;
            o[j][2] *= al1; o[j][3] *= al1;
        }

        // ---- O += (Ph+Pl) Vh (2 products) ----
        #pragma unroll
        for (int pk = 0; pk < 4; ++pk) {
            uint32_t phi[4], plo[4];
            pack_hilo(s[2*pk][0],   s[2*pk][1],   phi[0], plo[0]);
            pack_hilo(s[2*pk][2],   s[2*pk][3],   phi[1], plo[1]);
            pack_hilo(s[2*pk+1][0], s[2*pk+1][1], phi[2], plo[2]);
            pack_hilo(s[2*pk+1][2], s[2*pk+1][3], phi[3], plo[3]);
            #pragma unroll
            for (int j = 0; j < 16; ++j) {
                uint32_t bh2[2];
                ldm_x2t(bh2, bV + pk * (16 * FSTR) + bv_off + j * 16);
                mma_f16(o[j], phi, bh2);
                mma_f16(o[j], plo, bh2);
            }
        }
        __syncthreads();
    }

    // ---- epilogue: normalize, split to fp16 hi/lo ----
    const float inv0 = 1.f / l0, inv1 = 1.f / l1;
    #pragma unroll
    for (int j = 0; j < 16; ++j) {
        int col = j * 8 + (lane & 3) * 2;
        uint32_t hi, lo;
        pack_hilo(o[j][0] * inv0, o[j][1] * inv0, hi, lo);
        size_t off0 = (size_t)r0 * HID_ + h * HD_ + col;
        *(uint32_t*)&ath[off0] = hi;
        *(uint32_t*)&atl[off0] = lo;
        pack_hilo(o[j][2] * inv1, o[j][3] * inv1, hi, lo);
        size_t off1 = (size_t)(r0 + 8) * HID_ + h * HD_ + col;
        *(uint32_t*)&ath[off1] = hi;
        *(uint32_t*)&atl[off1] = lo;
    }
}

// ---------------------------------------------------------------------------
extern "C" void kernel_launch(void* const* d_in, const int* in_sizes, int n_in,
                              void* d_out, int out_size)
{
    const float* hs  = (const float*)d_in[0];
    const int*   pos = (const int*)  d_in[1];
    const float* Wq  = (const float*)d_in[3];
    const float* Wk  = (const float*)d_in[4];
    const float* Wv  = (const float*)d_in[5];
    const float* Wo  = (const float*)d_in[6];

    float* out  = (float*)d_out;                       // [S, HID]
    float* kout = out  + (size_t)S_ * HID_;            // [NH, S, HD] (repeated)
    float* vout = kout + (size_t)NH_ * S_ * HD_;       // [NH, S, HD] (repeated)

    float *qp, *kp, *vp;
    cudaGetSymbolAddress((void**)&qp, g_q);
    cudaGetSymbolAddress((void**)&kp, g_k);
    cudaGetSymbolAddress((void**)&vp, g_v);
    __half *hsh, *hsl, *wq, *wk, *wv, *wo, *ath, *atl;
    __half *qbh, *qbl, *kb, *vb;
    cudaGetSymbolAddress((void**)&hsh, g_hs_hi); cudaGetSymbolAddress((void**)&hsl, g_hs_lo);
    cudaGetSymbolAddress((void**)&wq, g_wq);
    cudaGetSymbolAddress((void**)&wk, g_wk);
    cudaGetSymbolAddress((void**)&wv, g_wv);
    cudaGetSymbolAddress((void**)&wo, g_wo);
    cudaGetSymbolAddress((void**)&ath, g_at_hi); cudaGetSymbolAddress((void**)&atl, g_at_lo);
    cudaGetSymbolAddress((void**)&qbh, g_qb_hi); cudaGetSymbolAddress((void**)&qbl, g_qb_lo);
    cudaGetSymbolAddress((void**)&kb, g_kb);
    cudaGetSymbolAddress((void**)&vb, g_vb);

    cudaFuncSetAttribute(qkv_gemm_kernel,
                         cudaFuncAttributeMaxDynamicSharedMemorySize, GEMM_SMEM);
    cudaFuncSetAttribute(gemm_mma_kernel,
                         cudaFuncAttributeMaxDynamicSharedMemorySize, GEMM_SMEM);
    cudaFuncSetAttribute(flash_tc_kernel,
                         cudaFuncAttributeMaxDynamicSharedMemorySize, FLASH_SMEM);

    // input conversions (transposes batched: 2 launches)
    conv_split_kernel<<<(S_*HID_/4)/256, 256>>>(hs, hsh, hsl);
    transpose_half2_kernel<<<dim3(HID_/32, HID_/32, 2), dim3(32,8)>>>(
        Wq, wq, Wo, wo, HID_, HID_);
    transpose_half2_kernel<<<dim3(KVD_/32, HID_/32, 2), dim3(32,8)>>>(
        Wk, wk, Wv, wv, HID_, KVD_);

    // fused QKV projection (2-product fp16)
    qkv_gemm_kernel<<<dim3(24, S_/128), 256, GEMM_SMEM>>>(
        hsh, hsl, wq, wk, wv, qp, kp, vp);

    // rope + layout (+ compact fp16 copies for flash)
    rope_q_kernel<<<(NH_*S_*64)/256, 256>>>(pos, qbh, qbl);
    rope_k_kernel<<<(NKV_*S_*64)/256, 256>>>(pos, kout, kb);
    copy_v_kernel<<<(NKV_*S_*32)/256, 256>>>(vout, vb);

    // attention (tensor core flash) -> fp16 hi/lo
    flash_tc_kernel<<<dim3(16, NH_), 256, FLASH_SMEM>>>(
        qbh, qbl, kb, vb, ath, atl);

    // output projection (2-product fp16)
    gemm_mma_kernel<<<dim3(HID_/128, S_/128), 256, GEMM_SMEM>>>(
        ath, atl, wo, out, HID_, HID_);
}

// round 9
// speedup vs baseline: 6.0799x; 1.0035x over previous
#include <cuda_runtime.h>
#include <cuda_fp16.h>
#include <math.h>
#include <stdint.h>

#define S_   2048
#define HID_ 2048
#define NH_  16
#define NKV_ 4
#define GRP_ (NH_/NKV_)   // 4
#define HD_  128
#define KVD_ (NKV_*HD_)   // 512

#define SCL_LOG2E 0.12751744f

// ---------------------------------------------------------------------------
// scratch (allocation-free: __device__ globals)
// ---------------------------------------------------------------------------
__device__ float g_q  [S_*HID_];
__device__ float g_k  [S_*KVD_];
__device__ float g_v  [S_*KVD_];

__device__ __half g_hs_hi[S_*HID_],  g_hs_lo[S_*HID_];
__device__ __half g_wq[HID_*HID_];
__device__ __half g_wk[KVD_*HID_];
__device__ __half g_wv[KVD_*HID_];
__device__ __half g_wo[HID_*HID_];
__device__ __half g_at_hi[S_*HID_],  g_at_lo[S_*HID_];

__device__ __half g_qb_hi[S_*HID_],  g_qb_lo[S_*HID_];
__device__ __half g_kb[NKV_*S_*HD_];
__device__ __half g_vb[NKV_*S_*HD_];

// ---------------------------------------------------------------------------
// PTX helpers (plain sm_103-safe)
// ---------------------------------------------------------------------------
__device__ __forceinline__ uint32_t smem_to_u32(const void* p) {
    uint32_t a;
    asm("{ .reg .u64 t; cvta.to.shared.u64 t, %1; cvt.u32.u64 %0, t; }"
        : "=r"(a) : "l"(p));
    return a;
}
__device__ __forceinline__ void cp16(uint32_t dst, const void* src) {
    asm volatile("cp.async.cg.shared.global [%0], [%1], 16;" :: "r"(dst), "l"(src));
}
#define CP_COMMIT() asm volatile("cp.async.commit_group;" ::: "memory")
#define CP_WAIT(n)  asm volatile("cp.async.wait_group %0;" :: "n"(n) : "memory")

__device__ __forceinline__ void ldm_x4(uint32_t* r, uint32_t addr) {
    asm volatile("ldmatrix.sync.aligned.m8n8.x4.shared.b16 {%0,%1,%2,%3}, [%4];"
        : "=r"(r[0]), "=r"(r[1]), "=r"(r[2]), "=r"(r[3]) : "r"(addr));
}
__device__ __forceinline__ void ldm_x2(uint32_t* r, uint32_t addr) {
    asm volatile("ldmatrix.sync.aligned.m8n8.x2.shared.b16 {%0,%1}, [%2];"
        : "=r"(r[0]), "=r"(r[1]) : "r"(addr));
}
__device__ __forceinline__ void ldm_x2t(uint32_t* r, uint32_t addr) {
    asm volatile("ldmatrix.sync.aligned.m8n8.x2.trans.shared.b16 {%0,%1}, [%2];"
        : "=r"(r[0]), "=r"(r[1]) : "r"(addr));
}
__device__ __forceinline__ void mma_f16(float* c, const uint32_t* a, const uint32_t* b) {
    asm volatile("mma.sync.aligned.m16n8k16.row.col.f32.f16.f16.f32 "
        "{%0,%1,%2,%3}, {%4,%5,%6,%7}, {%8,%9}, {%0,%1,%2,%3};"
        : "+f"(c[0]), "+f"(c[1]), "+f"(c[2]), "+f"(c[3])
        : "r"(a[0]), "r"(a[1]), "r"(a[2]), "r"(a[3]), "r"(b[0]), "r"(b[1]));
}

__device__ __forceinline__ void pack_hilo(float x, float y, uint32_t& hi, uint32_t& lo) {
    __half hx = __float2half_rn(x), hy = __float2half_rn(y);
    float rx = x - __half2float(hx), ry = y - __half2float(hy);
    __half lx = __float2half_rn(rx), ly = __float2half_rn(ry);
    union { __half2 h2; uint32_t u; } H, L;
    H.h2 = __halves2half2(hx, hy);
    L.h2 = __halves2half2(lx, ly);
    hi = H.u; lo = L.u;
}

__device__ __forceinline__ float fexp2(float x) {
    x = fmaxf(x, -126.0f);
    int e = __float2int_rn(x);
    float f = x - (float)e;
    float p = 0.0018775767f;
    p = fmaf(p, f, 0.0089893397f);
    p = fmaf(p, f, 0.0558040221f);
    p = fmaf(p, f, 0.2402264923f);
    p = fmaf(p, f, 0.6931471825f);
    p = fmaf(p, f, 1.0f);
    return __int_as_float(__float_as_int(p) + (e << 23));
}

__device__ __forceinline__ void split_f16(float v, __half* hi, __half* lo) {
    __half h = __float2half_rn(v);
    *hi = h;
    *lo = __float2half_rn(v - __half2float(h));
}

// ---------------------------------------------------------------------------
__global__ void conv_split_kernel(const float* __restrict__ src,
                                  __half* __restrict__ hi,
                                  __half* __restrict__ lo)
{
    int i = blockIdx.x * 256 + threadIdx.x;
    float4 v = ((const float4*)src)[i];
    float f[4] = {v.x, v.y, v.z, v.w};
    union { uint2 u; __half b[4]; } H, L;
    #pragma unroll
    for (int j = 0; j < 4; ++j) split_f16(f[j], &H.b[j], &L.b[j]);
    ((uint2*)hi)[i] = H.u;
    ((uint2*)lo)[i] = L.u;
}

__global__ void transpose_half2_kernel(const float* __restrict__ W0,
                                       __half* __restrict__ O0,
                                       const float* __restrict__ W1,
                                       __half* __restrict__ O1,
                                       int Kd, int Nd)
{
    __shared__ float t[32][33];
    const float* W = blockIdx.z ? W1 : W0;
    __half* out    = blockIdx.z ? O1 : O0;
    int bn = blockIdx.x * 32;
    int bk = blockIdx.y * 32;
    int x = threadIdx.x, y = threadIdx.y;
    #pragma unroll
    for (int i = 0; i < 32; i += 8)
        t[y + i][x] = W[(size_t)(bk + y + i) * Nd + bn + x];
    __syncthreads();
    #pragma unroll
    for (int i = 0; i < 32; i += 8)
        out[(size_t)(bn + y + i) * Kd + bk + x] = __float2half_rn(t[x][y + i]);
}

// ---------------------------------------------------------------------------
// mma.sync GEMM: C = (Ah+Al) @ Bh^T, 2 products, dependency-split passes.
// ---------------------------------------------------------------------------
#define TILE_B   10240
#define BUF_B    (3*TILE_B)
#define GEMM_SMEM (3*BUF_B)

__device__ __forceinline__ void load_tile_async(uint32_t sdst,
                                                const __half* g,
                                                int ldk, int tid)
{
    int r   = tid >> 2;
    int seg = tid & 3;
    #pragma unroll
    for (int h = 0; h < 2; ++h) {
        int row = r + h * 64;
        cp16(sdst + row * 80 + seg * 16, g + (size_t)row * ldk + seg * 8);
    }
}

__device__ __forceinline__ void load_stage(uint32_t buf,
                                           const __half* Ahi, const __half* Alo,
                                           const __half* Bh, int k0, int K, int tid)
{
    load_tile_async(buf,            Ahi + k0, K, tid);
    load_tile_async(buf +   TILE_B, Alo + k0, K, tid);
    load_tile_async(buf + 2*TILE_B, Bh  + k0, K, tid);
}

__device__ __forceinline__ void gemm_body(
    uint32_t sb,
    const __half* Ahi, const __half* Alo, const __half* Bh,
    float* C, int N, int K, int tid)
{
    const int lane = tid & 31, wid = tid >> 5;
    const int wm = wid & 1, wn = wid >> 1;

    float acc[4][4][4];
    #pragma unroll
    for (int mi = 0; mi < 4; ++mi)
        #pragma unroll
        for (int ni = 0; ni < 4; ++ni)
            #pragma unroll
            for (int q = 0; q < 4; ++q) acc[mi][ni][q] = 0.f;

    const int T = K / 32;
    load_stage(sb,         Ahi, Alo, Bh, 0,  K, tid);
    CP_COMMIT();
    load_stage(sb + BUF_B, Ahi, Alo, Bh, 32, K, tid);
    CP_COMMIT();

    const uint32_t a_lane_off = (uint32_t)((lane & 15) * 80 + (lane >> 4) * 16);
    const uint32_t b_lane_off = (uint32_t)((lane & 7) * 80 + ((lane >> 3) & 1) * 16);

    int bufidx = 0;
    for (int kt = 0; kt < T; ++kt) {
        CP_WAIT(1);
        __syncthreads();

        if (kt + 2 < T) {
            int nbi = bufidx + 2; if (nbi >= 3) nbi -= 3;
            load_stage(sb + nbi * BUF_B, Ahi, Alo, Bh, (kt + 2) * 32, K, tid);
            CP_COMMIT();
        }

        uint32_t buf = sb + bufidx * BUF_B;
        #pragma unroll
        for (int ks = 0; ks < 2; ++ks) {
            uint32_t ah[4][4], al[4][4], bh[4][2];
            uint32_t abase = buf + wm * (64 * 80) + a_lane_off + ks * 32;
            #pragma unroll
            for (int mi = 0; mi < 4; ++mi) {
                ldm_x4(ah[mi], abase + mi * (16 * 80));
                ldm_x4(al[mi], abase + TILE_B + mi * (16 * 80));
            }
            uint32_t bbase = buf + 2*TILE_B + wn * (32 * 80) + b_lane_off + ks * 32;
            #pragma unroll
            for (int ni = 0; ni < 4; ++ni)
                ldm_x2(bh[ni], bbase + ni * (8 * 80));
            // hi pass — 16 independent accumulators
            #pragma unroll
            for (int mi = 0; mi < 4; ++mi)
                #pragma unroll
                for (int ni = 0; ni < 4; ++ni)
                    mma_f16(acc[mi][ni], ah[mi], bh[ni]);
            // lo pass — same acc writes separated by 15 MMAs
            #pragma unroll
            for (int mi = 0; mi < 4; ++mi)
                #pragma unroll
                for (int ni = 0; ni < 4; ++ni)
                    mma_f16(acc[mi][ni], al[mi], bh[ni]);
        }
        if (++bufidx == 3) bufidx = 0;
    }

    #pragma unroll
    for (int mi = 0; mi < 4; ++mi) {
        int row = wm * 64 + mi * 16 + (lane >> 2);
        #pragma unroll
        for (int ni = 0; ni < 4; ++ni) {
            int col = wn * 32 + ni * 8 + (lane & 3) * 2;
            *(float2*)&C[(size_t)row * N + col] =
                make_float2(acc[mi][ni][0], acc[mi][ni][1]);
            *(float2*)&C[(size_t)(row + 8) * N + col] =
                make_float2(acc[mi][ni][2], acc[mi][ni][3]);
        }
    }
}

__global__ __launch_bounds__(256, 2)
void qkv_gemm_kernel(const __half* __restrict__ Ahi,
                     const __half* __restrict__ Alo,
                     const __half* __restrict__ Wq,
                     const __half* __restrict__ Wk,
                     const __half* __restrict__ Wv,
                     float* __restrict__ Cq, float* __restrict__ Ck,
                     float* __restrict__ Cv)
{
    extern __shared__ char smp[];
    uint32_t sb = smem_to_u32(smp);
    const int nb = blockIdx.x;
    const int bm = blockIdx.y * 128;
    const __half* Bh;
    float* C;
    int N, bn;
    if (nb < 16)      { Bh = Wq; C = Cq; N = HID_; bn = nb * 128; }
    else if (nb < 20) { Bh = Wk; C = Ck; N = KVD_; bn = (nb - 16) * 128; }
    else              { Bh = Wv; C = Cv; N = KVD_; bn = (nb - 20) * 128; }
    gemm_body(sb,
              Ahi + (size_t)bm * HID_, Alo + (size_t)bm * HID_,
              Bh + (size_t)bn * HID_,
              C + (size_t)bm * N + bn, N, HID_, threadIdx.x);
}

__global__ __launch_bounds__(256, 2)
void gemm_mma_kernel(const __half* __restrict__ Ahi,
                     const __half* __restrict__ Alo,
                     const __half* __restrict__ Bh,
                     float* __restrict__ C, int N, int K)
{
    extern __shared__ char smp[];
    uint32_t sb = smem_to_u32(smp);
    const int bm = blockIdx.y * 128, bn = blockIdx.x * 128;
    gemm_body(sb,
              Ahi + (size_t)bm * K, Alo + (size_t)bm * K,
              Bh + (size_t)bn * K,
              C + (size_t)bm * N + bn, N, K, threadIdx.x);
}

// ---------------------------------------------------------------------------
// RoPE
// ---------------------------------------------------------------------------
__device__ __forceinline__ void rope_pair(float x1, float x2, int pos, int d,
                                          float& o1, float& o2)
{
    float inv = exp2f((float)d * (-13.287712379549449f / 64.0f));
    float ang = (float)pos * inv;
    float sn, cs;
    sincosf(ang, &sn, &cs);
    o1 = x1 * cs - x2 * sn;
    o2 = x1 * sn + x2 * cs;
}

__global__ void rope_q_kernel(const int* __restrict__ positions,
                              __half* __restrict__ qh,
                              __half* __restrict__ ql)
{
    int idx = blockIdx.x * blockDim.x + threadIdx.x;
    int d = idx & 63;
    int s = (idx >> 6) & (S_ - 1);
    int h = idx >> 17;
    size_t base = (size_t)s * HID_ + h * HD_;
    float x1 = g_q[base + d], x2 = g_q[base + d + 64];
    float o1, o2;
    rope_pair(x1, x2, positions[s], d, o1, o2);
    o1 *= SCL_LOG2E; o2 *= SCL_LOG2E;
    split_f16(o1, &qh[base + d],      &ql[base + d]);
    split_f16(o2, &qh[base + d + 64], &ql[base + d + 64]);
}

__global__ void rope_k_kernel(const int* __restrict__ positions,
                              float* __restrict__ kout,
                              __half* __restrict__ kb)
{
    int idx = blockIdx.x * blockDim.x + threadIdx.x;
    int d  = idx & 63;
    int s  = (idx >> 6) & (S_ - 1);
    int kv = idx >> 17;
    size_t src = (size_t)s * KVD_ + kv * HD_;
    float x1 = g_k[src + d], x2 = g_k[src + d + 64];
    float o1, o2;
    rope_pair(x1, x2, positions[s], d, o1, o2);
    #pragma unroll
    for (int g = 0; g < GRP_; ++g) {
        size_t dst = ((size_t)(kv * GRP_ + g) * S_ + s) * HD_;
        kout[dst + d] = o1; kout[dst + d + 64] = o2;
    }
    size_t cb = ((size_t)kv * S_ + s) * HD_;
    kb[cb + d]      = __float2half_rn(o1);
    kb[cb + d + 64] = __float2half_rn(o2);
}

__global__ void copy_v_kernel(float* __restrict__ vout,
                              __half* __restrict__ vb)
{
    int idx = blockIdx.x * blockDim.x + threadIdx.x;
    int d4 = idx & 31;
    int s  = (idx >> 5) & (S_ - 1);
    int kv = idx >> 16;
    float4 v = *(const float4*)&g_v[(size_t)s * KVD_ + kv * HD_ + d4 * 4];
    #pragma unroll
    for (int g = 0; g < GRP_; ++g)
        *(float4*)&vout[((size_t)(kv * GRP_ + g) * S_ + s) * HD_ + d4 * 4] = v;
    size_t cb = ((size_t)kv * S_ + s) * HD_ + d4 * 4;
    float f[4] = {v.x, v.y, v.z, v.w};
    union { uint2 u; __half b[4]; } H;
    #pragma unroll
    for (int j = 0; j < 4; ++j) H.b[j] = __float2half_rn(f[j]);
    *(uint2*)&vb[cb] = H.u;
}

// ---------------------------------------------------------------------------
// Tensor-core flash attention: BQ=128, BK=64, HD=128, 8 warps.
// Dependency-split hi/lo passes in QK and PV.
// ---------------------------------------------------------------------------
#define FSTR  272
#define FQ_B  (128*FSTR)
#define FKV_B (64*FSTR)
#define FLASH_SMEM (2*FQ_B + 4*FKV_B)

__global__ __launch_bounds__(256, 1)
void flash_tc_kernel(const __half* __restrict__ qhp,
                     const __half* __restrict__ qlp,
                     const __half* __restrict__ khp,
                     const __half* __restrict__ vhp,
                     __half* __restrict__ ath,
                     __half* __restrict__ atl)
{
    extern __shared__ char smp[];
    const uint32_t sb = smem_to_u32(smp);
    const int tid = threadIdx.x, lane = tid & 31, w = tid >> 5;
    const int qb = 15 - blockIdx.x, h = blockIdx.y, kv = h >> 2;
    const int q0 = qb * 128;

    const uint32_t sQh = sb, sQl = sb + FQ_B;
    const uint32_t sKV = sb + 2 * FQ_B;

    {
        const __half* srch = qhp + (size_t)q0 * HID_ + h * HD_;
        const __half* srcl = qlp + (size_t)q0 * HID_ + h * HD_;
        #pragma unroll
        for (int c = tid; c < 2048; c += 256) {
            int r = c >> 4, seg = c & 15;
            cp16(sQh + r * FSTR + seg * 16, srch + (size_t)r * HID_ + seg * 8);
            cp16(sQl + r * FSTR + seg * 16, srcl + (size_t)r * HID_ + seg * 8);
        }
    }
    const __half* kb = khp + (size_t)kv * S_ * HD_;
    const __half* vb = vhp + (size_t)kv * S_ * HD_;

    auto load_kv = [&](int kt, uint32_t buf) {
        #pragma unroll
        for (int c = tid; c < 1024; c += 256) {
            int r = c >> 4, seg = c & 15;
            size_t g = (size_t)(kt * 64 + r) * HD_ + seg * 8;
            uint32_t so = r * FSTR + seg * 16;
            cp16(buf + so,         kb + g);
            cp16(buf + FKV_B + so, vb + g);
        }
    };
    load_kv(0, sKV);
    CP_COMMIT();

    float o[16][4];
    #pragma unroll
    for (int j = 0; j < 16; ++j)
        #pragma unroll
        for (int q = 0; q < 4; ++q) o[j][q] = 0.f;
    float m0 = -1e30f, m1 = -1e30f, l0 = 0.f, l1 = 0.f;

    const int last = 2 * qb + 1;
    const uint32_t a_off  = (lane & 15) * FSTR + (lane >> 4) * 16;
    const uint32_t bk_off = (lane & 7) * FSTR + ((lane >> 3) & 1) * 16;
    const uint32_t bv_off = (lane & 15) * FSTR;
    const int r0 = q0 + w * 16 + (lane >> 2);

    for (int kt = 0; kt <= last; ++kt) {
        if (kt < last) {
            load_kv(kt + 1, sKV + ((kt + 1) & 1) * 2 * FKV_B);
            CP_COMMIT();
            CP_WAIT(1);
        } else {
            CP_WAIT(0);
        }
        __syncthreads();

        const uint32_t bK = sKV + (kt & 1) * 2 * FKV_B;
        const uint32_t bV = bK + FKV_B;

        // ---- scores S = (Qh+Ql) Kh^T (dependency-split) ----
        float s[8][4];
        #pragma unroll
        for (int j = 0; j < 8; ++j)
            #pragma unroll
            for (int q = 0; q < 4; ++q) s[j][q] = 0.f;

        #pragma unroll
        for (int ks = 0; ks < 8; ++ks) {
            uint32_t ah[4], al[4], bh2[8][2];
            ldm_x4(ah, sQh + w * (16 * FSTR) + a_off + ks * 32);
            ldm_x4(al, sQl + w * (16 * FSTR) + a_off + ks * 32);
            #pragma unroll
            for (int j = 0; j < 8; ++j)
                ldm_x2(bh2[j], bK + j * (8 * FSTR) + bk_off + ks * 32);
            #pragma unroll
            for (int j = 0; j < 8; ++j)
                mma_f16(s[j], ah, bh2[j]);
            #pragma unroll
            for (int j = 0; j < 8; ++j)
                mma_f16(s[j], al, bh2[j]);
        }

        // ---- causal mask ----
        if (kt >= 2 * qb) {
            #pragma unroll
            for (int j = 0; j < 8; ++j) {
                int col = kt * 64 + j * 8 + (lane & 3) * 2;
                if (col     > r0)     s[j][0] = -3e4f;
                if (col + 1 > r0)     s[j][1] = -3e4f;
                if (col     > r0 + 8) s[j][2] = -3e4f;
                if (col + 1 > r0 + 8) s[j][3] = -3e4f;
            }
        }

        // ---- row max ----
        float mx0 = -3e4f, mx1 = -3e4f;
        #pragma unroll
        for (int j = 0; j < 8; ++j) {
            mx0 = fmaxf(mx0, fmaxf(s[j][0], s[j][1]));
            mx1 = fmaxf(mx1, fmaxf(s[j][2], s[j][3]));
        }
        mx0 = fmaxf(mx0, __shfl_xor_sync(0xffffffffu, mx0, 1));
        mx0 = fmaxf(mx0, __shfl_xor_sync(0xffffffffu, mx0, 2));
        mx1 = fmaxf(mx1, __shfl_xor_sync(0xffffffffu, mx1, 1));
        mx1 = fmaxf(mx1, __shfl_xor_sync(0xffffffffu, mx1, 2));

        const float mn0 = fmaxf(m0, mx0), mn1 = fmaxf(m1, mx1);
        const float al0 = fexp2(m0 - mn0), al1 = fexp2(m1 - mn1);
        m0 = mn0; m1 = mn1;

        // ---- exp + row sum ----
        float sum0 = 0.f, sum1 = 0.f;
        #pragma unroll
        for (int j = 0; j < 8; ++j) {
            s[j][0] = fexp2(s[j][0] - mn0);
            s[j][1] = fexp2(s[j][1] - mn0);
            s[j][2] = fexp2(s[j][2] - mn1);
            s[j][3] = fexp2(s[j][3] - mn1);
            sum0 += s[j][0] + s[j][1];
            sum1 += s[j][2] + s[j][3];
        }
        sum0 += __shfl_xor_sync(0xffffffffu, sum0, 1);
        sum0 += __shfl_xor_sync(0xffffffffu, sum0, 2);
        sum1 += __shfl_xor_sync(0xffffffffu, sum1, 1);
        sum1 += __shfl_xor_sync(0xffffffffu, sum1, 2);
        l0 = l0 * al0 + sum0;
        l1 = l1 * al1 + sum1;

        // ---- rescale O ----
        #pragma unroll
        for (int j = 0; j < 16; ++j) {
            o[j][0] *= al0; o[j][1] *= al0;
            o[j][2] *= al1; o[j][3] *= al1;
        }

        // ---- O += (Ph+Pl) Vh (dependency-split) ----
        #pragma unroll
        for (int pk = 0; pk < 4; ++pk) {
            uint32_t phi[4], plo[4], vv[16][2];
            pack_hilo(s[2*pk][0],   s[2*pk][1],   phi[0], plo[0]);
            pack_hilo(s[2*pk][2],   s[2*pk][3],   phi[1], plo[1]);
            pack_hilo(s[2*pk+1][0], s[2*pk+1][1], phi[2], plo[2]);
            pack_hilo(s[2*pk+1][2], s[2*pk+1][3], phi[3], plo[3]);
            #pragma unroll
            for (int j = 0; j < 16; ++j) {
                ldm_x2t(vv[j], bV + pk * (16 * FSTR) + bv_off + j * 16);
                mma_f16(o[j], phi, vv[j]);
            }
            #pragma unroll
            for (int j = 0; j < 16; ++j)
                mma_f16(o[j], plo, vv[j]);
        }
        __syncthreads();
    }

    // ---- epilogue ----
    const float inv0 = 1.f / l0, inv1 = 1.f / l1;
    #pragma unroll
    for (int j = 0; j < 16; ++j) {
        int col = j * 8 + (lane & 3) * 2;
        uint32_t hi, lo;
        pack_hilo(o[j][0] * inv0, o[j][1] * inv0, hi, lo);
        size_t off0 = (size_t)r0 * HID_ + h * HD_ + col;
        *(uint32_t*)&ath[off0] = hi;
        *(uint32_t*)&atl[off0] = lo;
        pack_hilo(o[j][2] * inv1, o[j][3] * inv1, hi, lo);
        size_t off1 = (size_t)(r0 + 8) * HID_ + h * HD_ + col;
        *(uint32_t*)&ath[off1] = hi;
        *(uint32_t*)&atl[off1] = lo;
    }
}

// ---------------------------------------------------------------------------
extern "C" void kernel_launch(void* const* d_in, const int* in_sizes, int n_in,
                              void* d_out, int out_size)
{
    const float* hs  = (const float*)d_in[0];
    const int*   pos = (const int*)  d_in[1];
    const float* Wq  = (const float*)d_in[3];
    const float* Wk  = (const float*)d_in[4];
    const float* Wv  = (const float*)d_in[5];
    const float* Wo  = (const float*)d_in[6];

    float* out  = (float*)d_out;
    float* kout = out  + (size_t)S_ * HID_;
    float* vout = kout + (size_t)NH_ * S_ * HD_;

    float *qp, *kp, *vp;
    cudaGetSymbolAddress((void**)&qp, g_q);
    cudaGetSymbolAddress((void**)&kp, g_k);
    cudaGetSymbolAddress((void**)&vp, g_v);
    __half *hsh, *hsl, *wq, *wk, *wv, *wo, *ath, *atl;
    __half *qbh, *qbl, *kb, *vb;
    cudaGetSymbolAddress((void**)&hsh, g_hs_hi); cudaGetSymbolAddress((void**)&hsl, g_hs_lo);
    cudaGetSymbolAddress((void**)&wq, g_wq);
    cudaGetSymbolAddress((void**)&wk, g_wk);
    cudaGetSymbolAddress((void**)&wv, g_wv);
    cudaGetSymbolAddress((void**)&wo, g_wo);
    cudaGetSymbolAddress((void**)&ath, g_at_hi); cudaGetSymbolAddress((void**)&atl, g_at_lo);
    cudaGetSymbolAddress((void**)&qbh, g_qb_hi); cudaGetSymbolAddress((void**)&qbl, g_qb_lo);
    cudaGetSymbolAddress((void**)&kb, g_kb);
    cudaGetSymbolAddress((void**)&vb, g_vb);

    cudaFuncSetAttribute(qkv_gemm_kernel,
                         cudaFuncAttributeMaxDynamicSharedMemorySize, GEMM_SMEM);
    cudaFuncSetAttribute(gemm_mma_kernel,
                         cudaFuncAttributeMaxDynamicSharedMemorySize, GEMM_SMEM);
    cudaFuncSetAttribute(flash_tc_kernel,
                         cudaFuncAttributeMaxDynamicSharedMemorySize, FLASH_SMEM);

    conv_split_kernel<<<(S_*HID_/4)/256, 256>>>(hs, hsh, hsl);
    transpose_half2_kernel<<<dim3(HID_/32, HID_/32, 2), dim3(32,8)>>>(
        Wq, wq, Wo, wo, HID_, HID_);
    transpose_half2_kernel<<<dim3(KVD_/32, HID_/32, 2), dim3(32,8)>>>(
        Wk, wk, Wv, wv, HID_, KVD_);

    qkv_gemm_kernel<<<dim3(24, S_/128), 256, GEMM_SMEM>>>(
        hsh, hsl, wq, wk, wv, qp, kp, vp);

    rope_q_kernel<<<(NH_*S_*64)/256, 256>>>(pos, qbh, qbl);
    rope_k_kernel<<<(NKV_*S_*64)/256, 256>>>(pos, kout, kb);
    copy_v_kernel<<<(NKV_*S_*32)/256, 256>>>(vout, vb);

    flash_tc_kernel<<<dim3(16, NH_), 256, FLASH_SMEM>>>(
        qbh, qbl, kb, vb, ath, atl);

    gemm_mma_kernel<<<dim3(HID_/128, S_/128), 256, GEMM_SMEM>>>(
        ath, atl, wo, out, HID_, HID_);
}